// round 9
// baseline (speedup 1.0000x reference)
#include <cuda_runtime.h>
#include <math.h>
#include <stdint.h>

#define Bq   8
#define Tq   500
#define Uq   120
#define UP1  121
#define Vq   128
#define Hq   320
#define G4   1280
#define DIN  80
#define VM1  127
#define DTq  121

#define NTC  4      // tail chunks (joint/alpha overlap)
#define TCJ  125    // t per tail chunk

// ---------------- static device scratch ----------------
__device__ float g_xp0[Bq * Tq * G4];
__device__ float g_h0 [Bq * Tq * Hq];
__device__ float g_xp1[Bq * Tq * G4];
__device__ float g_h1 [Bq * Tq * Hq];
__device__ float g_enc[Bq * Tq * Vq];
__device__ float g_xpd[Bq * UP1 * G4];
__device__ float g_hd [Bq * UP1 * Hq];
__device__ float g_dec[Bq * UP1 * Vq];
__device__ float g_lb [Bq * Tq * UP1];
__device__ float g_ly [Bq * Tq * Uq];
__device__ float g_nll[Bq];
__device__ float g_alpha[Bq * 128];

__device__ __forceinline__ float sig_f(float x)
{
    return __fdividef(1.f, 1.f + __expf(-x));
}
__device__ __forceinline__ float tanh_f(float x)
{
    float e = __expf(2.f * fabsf(x));
    float r = 1.f - __fdividef(2.f, e + 1.f);
    return copysignf(r, x);
}

// ---------------- tiled GEMM: C[M,N] = A[M,K] @ B[N,K]^T + b1 + b2 ----------------
#define GBM 128
#define GBN 64
#define GBK 16

__global__ void __launch_bounds__(256) gemm_nt(const float* __restrict__ A,
                                               const float* __restrict__ Bm,
                                               const float* __restrict__ b1,
                                               const float* __restrict__ b2,
                                               float* __restrict__ C,
                                               int M, int N, int K)
{
    __shared__ float As[GBK][GBM + 4];
    __shared__ float Bs[GBK][GBN + 4];
    int tid = threadIdx.x;
    int bm = blockIdx.y * GBM;
    int bn = blockIdx.x * GBN;
    int tx = tid & 15, ty = tid >> 4;

    float acc[8][4];
#pragma unroll
    for (int i = 0; i < 8; i++)
#pragma unroll
        for (int j = 0; j < 4; j++) acc[i][j] = 0.f;

    for (int k0 = 0; k0 < K; k0 += GBK) {
#pragma unroll
        for (int l = 0; l < 8; l++) {
            int idx = l * 256 + tid;
            int am = idx >> 4, ak = idx & 15;
            float v = 0.f;
            if (bm + am < M && k0 + ak < K) v = A[(size_t)(bm + am) * K + k0 + ak];
            As[ak][am] = v;
        }
#pragma unroll
        for (int l = 0; l < 4; l++) {
            int idx = l * 256 + tid;
            int bnn = idx >> 4, bk = idx & 15;
            float v = 0.f;
            if (bn + bnn < N && k0 + bk < K) v = Bm[(size_t)(bn + bnn) * K + k0 + bk];
            Bs[bk][bnn] = v;
        }
        __syncthreads();
#pragma unroll
        for (int k = 0; k < GBK; k++) {
            float4 a0 = *(const float4*)&As[k][ty * 8];
            float4 a1 = *(const float4*)&As[k][ty * 8 + 4];
            float4 bv = *(const float4*)&Bs[k][tx * 4];
            float af[8] = {a0.x, a0.y, a0.z, a0.w, a1.x, a1.y, a1.z, a1.w};
            float bf[4] = {bv.x, bv.y, bv.z, bv.w};
#pragma unroll
            for (int i = 0; i < 8; i++)
#pragma unroll
                for (int j = 0; j < 4; j++) acc[i][j] += af[i] * bf[j];
        }
        __syncthreads();
    }

    int n0 = bn + tx * 4;
    float bias[4];
#pragma unroll
    for (int j = 0; j < 4; j++)
        bias[j] = (b1 ? b1[n0 + j] : 0.f) + (b2 ? b2[n0 + j] : 0.f);

#pragma unroll
    for (int i = 0; i < 8; i++) {
        int m = bm + ty * 8 + i;
        if (m >= M) continue;
        float4 r;
        r.x = acc[i][0] + bias[0];
        r.y = acc[i][1] + bias[1];
        r.z = acc[i][2] + bias[2];
        r.w = acc[i][3] + bias[3];
        *(float4*)&C[(size_t)m * N + n0] = r;
    }
}

// ---------------- LSTM: 16-CTA cluster/batch, BULK h-broadcast --------------------------
// 20 units/CTA; thread = (s = tid&15 K-slice of 20, rg = tid>>4 unit). 80 weight floats
// register-resident. Broadcast: stage 20 h values in smem, then 16 threads each issue ONE
// 80-byte cp.async.bulk to a peer CTA (16 transactions/CTA/step instead of 320 st.async).
__global__ void __launch_bounds__(320, 1)
lstm16_kernel(const float* __restrict__ Whh, const float* __restrict__ xproj,
              float* __restrict__ hout, int T)
{
    __shared__ __align__(16) float hbuf[2][Hq];          // buffer stride 1280 B
    __shared__ __align__(16) float hstage[2][32];        // buffer stride 128 B (20 used)
    __shared__ __align__(8) unsigned long long mbars[2];

    unsigned rank;
    asm("mov.u32 %0, %%cluster_ctarank;" : "=r"(rank));
    int batch = blockIdx.x >> 4;

    int tid = threadIdx.x;
    int s   = tid & 15;           // K-slice (20 wide)
    int rg  = tid >> 4;           // local unit 0..19
    int unit = (int)rank * 20 + rg;

    // register-resident weights: 4 gates x 20 K = 80 floats as 40 u64
    unsigned long long w[4][10];
#pragma unroll
    for (int r = 0; r < 4; r++) {
        const ulonglong2* p = reinterpret_cast<const ulonglong2*>(
            Whh + (size_t)(r * Hq + unit) * Hq + s * 20);
#pragma unroll
        for (int i = 0; i < 5; i++) {
            ulonglong2 u = p[i];
            w[r][2 * i] = u.x; w[r][2 * i + 1] = u.y;
        }
    }

    hbuf[0][tid] = 0.f;
    float c = 0.f;

    unsigned mb_local = (unsigned)__cvta_generic_to_shared(&mbars[0]);
    if (tid == 0) {
        asm volatile("mbarrier.init.shared.b64 [%0], 1;" :: "r"(mb_local) : "memory");
        asm volatile("mbarrier.init.shared.b64 [%0], 1;" :: "r"(mb_local + 8) : "memory");
    }

    const float* xpb = xproj + ((size_t)batch * T) * G4 + unit;
    float xg0 = 0.f, xg1 = 0.f, xg2 = 0.f, xg3 = 0.f;
    if (s == 0) {
        xg0 = __ldg(xpb);
        xg1 = __ldg(xpb + Hq);
        xg2 = __ldg(xpb + 2 * Hq);
        xg3 = __ldg(xpb + 3 * Hq);
    }

    // thread tid<16 sends this CTA's 20-value chunk to peer 'tid'
    unsigned src_base = (unsigned)__cvta_generic_to_shared(&hstage[0][0]);
    unsigned dst_local = (unsigned)__cvta_generic_to_shared(&hbuf[0][0]) + rank * 80u;
    unsigned rdst = 0, rmb = 0;
    if (tid < 16) {
        asm("mapa.shared::cluster.u32 %0, %1, %2;" : "=r"(rdst) : "r"(dst_local), "r"(tid));
        asm("mapa.shared::cluster.u32 %0, %1, %2;" : "=r"(rmb) : "r"(mb_local), "r"(tid));
    }

    __syncthreads();
    asm volatile("barrier.cluster.arrive.aligned;" ::: "memory");
    asm volatile("barrier.cluster.wait.aligned;" ::: "memory");

    unsigned ph0 = 0, ph1 = 0;

    for (int t = 0; t < T; t++) {
        int cur = t & 1, nxt = cur ^ 1;
        int not_last = (t + 1 < T);

        if (not_last && tid == 0)
            asm volatile("mbarrier.arrive.expect_tx.shared.b64 _, [%0], 1280;"
                         :: "r"(mb_local + (unsigned)nxt * 8) : "memory");

        // matvec: 4 gate rows x 20 K, f32x2 packed
        const ulonglong2* h2 =
            reinterpret_cast<const ulonglong2*>(&hbuf[cur][s * 20]);
        unsigned long long a0 = 0ULL, a1 = 0ULL, a2 = 0ULL, a3 = 0ULL;
#pragma unroll
        for (int i = 0; i < 5; i++) {
            ulonglong2 hv = h2[i];
            asm("fma.rn.f32x2 %0, %1, %2, %0;" : "+l"(a0) : "l"(w[0][2*i]),   "l"(hv.x));
            asm("fma.rn.f32x2 %0, %1, %2, %0;" : "+l"(a1) : "l"(w[1][2*i]),   "l"(hv.x));
            asm("fma.rn.f32x2 %0, %1, %2, %0;" : "+l"(a2) : "l"(w[2][2*i]),   "l"(hv.x));
            asm("fma.rn.f32x2 %0, %1, %2, %0;" : "+l"(a3) : "l"(w[3][2*i]),   "l"(hv.x));
            asm("fma.rn.f32x2 %0, %1, %2, %0;" : "+l"(a0) : "l"(w[0][2*i+1]), "l"(hv.y));
            asm("fma.rn.f32x2 %0, %1, %2, %0;" : "+l"(a1) : "l"(w[1][2*i+1]), "l"(hv.y));
            asm("fma.rn.f32x2 %0, %1, %2, %0;" : "+l"(a2) : "l"(w[2][2*i+1]), "l"(hv.y));
            asm("fma.rn.f32x2 %0, %1, %2, %0;" : "+l"(a3) : "l"(w[3][2*i+1]), "l"(hv.y));
        }
        float g0, g1, g2, g3;
        {
            unsigned lo, hi;
            asm("mov.b64 {%0,%1}, %2;" : "=r"(lo), "=r"(hi) : "l"(a0));
            g0 = __uint_as_float(lo) + __uint_as_float(hi);
            asm("mov.b64 {%0,%1}, %2;" : "=r"(lo), "=r"(hi) : "l"(a1));
            g1 = __uint_as_float(lo) + __uint_as_float(hi);
            asm("mov.b64 {%0,%1}, %2;" : "=r"(lo), "=r"(hi) : "l"(a2));
            g2 = __uint_as_float(lo) + __uint_as_float(hi);
            asm("mov.b64 {%0,%1}, %2;" : "=r"(lo), "=r"(hi) : "l"(a3));
            g3 = __uint_as_float(lo) + __uint_as_float(hi);
        }
        if (s == 0) { g0 += xg0; g1 += xg1; g2 += xg2; g3 += xg3; }

        // prefetch next-step xproj
        if (s == 0 && not_last) {
            const float* xq = xpb + (size_t)(t + 1) * G4;
            xg0 = __ldg(xq);
            xg1 = __ldg(xq + Hq);
            xg2 = __ldg(xq + 2 * Hq);
            xg3 = __ldg(xq + 3 * Hq);
        }

        // butterfly over the 16 slice lanes
#pragma unroll
        for (int d = 1; d < 16; d <<= 1) {
            g0 += __shfl_xor_sync(0xffffffffu, g0, d);
            g1 += __shfl_xor_sync(0xffffffffu, g1, d);
            g2 += __shfl_xor_sync(0xffffffffu, g2, d);
            g3 += __shfl_xor_sync(0xffffffffu, g3, d);
        }

        float i_ = sig_f(g0);
        float f_ = sig_f(g1);
        float gg = tanh_f(g2);
        float o_ = sig_f(g3);
        c = f_ * c + i_ * gg;
        float h = o_ * tanh_f(c);

        if (s == 0) {
            hstage[cur][rg] = h;      // double-buffered: safe reuse proven by phase ring
            hout[((size_t)batch * T + t) * Hq + unit] = h;
        }
        __syncthreads();              // all 20 units staged

        if (not_last) {
            if (tid < 16) {
                asm volatile("fence.proxy.async.shared::cta;" ::: "memory");
                asm volatile(
                    "cp.async.bulk.shared::cluster.shared::cta.mbarrier::complete_tx::bytes "
                    "[%0], [%1], 80, [%2];"
                    :: "r"(rdst + (unsigned)nxt * 1280u),
                       "r"(src_base + (unsigned)cur * 128u),
                       "r"(rmb + (unsigned)nxt * 8u) : "memory");
            }
            unsigned par = nxt ? ph1 : ph0;
            unsigned mb  = mb_local + (unsigned)nxt * 8;
            asm volatile(
                "{\n\t.reg .pred P;\n\t"
                "WL_%=:\n\t"
                "mbarrier.try_wait.parity.acquire.cta.shared::cta.b64 P, [%0], %1, 0x989680;\n\t"
                "@!P bra WL_%=;\n\t}"
                :: "r"(mb), "r"(par) : "memory");
            if (nxt) ph1 ^= 1; else ph0 ^= 1;
        }
    }
}

// ---------------- decoder xproj via embedding gather (one-hot rows) ----------------
__global__ void __launch_bounds__(256) xpd_kernel(const int* __restrict__ ys,
                                                  const float* __restrict__ Wih,
                                                  const float* __restrict__ bih,
                                                  const float* __restrict__ bhh)
{
    int b = blockIdx.x / UP1, u = blockIdx.x % UP1;
    int id = (u == 0) ? 0 : ys[b * Uq + u - 1];
    float* dst = g_xpd + ((size_t)b * UP1 + u) * G4;
    for (int g = threadIdx.x; g < G4; g += 256) {
        float v = bih[g] + bhh[g];
        if (id > 0) v += Wih[(size_t)g * VM1 + (id - 1)];
        dst[g] = v;
    }
}

// ---------------- joint + log-softmax -> lb/ly, per t-chunk ----------------
__global__ void __launch_bounds__(128) joint_kernel(const int* __restrict__ ys, int t0)
{
    int b = blockIdx.y;
    int t = t0 + blockIdx.x * 4 + (threadIdx.x >> 5);
    if (t >= t0 + TCJ || t >= Tq) return;
    int lane = threadIdx.x & 31;

    const float* e = g_enc + ((size_t)b * Tq + t) * Vq;
    float e0 = e[lane], e1 = e[32 + lane], e2 = e[64 + lane], e3 = e[96 + lane];
    float* lbp = g_lb + ((size_t)b * Tq + t) * UP1;
    float* lyp = g_ly + ((size_t)b * Tq + t) * Uq;

    for (int u = 0; u < UP1; u++) {
        const float* d = g_dec + ((size_t)b * UP1 + u) * Vq;
        float j0 = e0 + d[lane];
        float j1 = e1 + d[32 + lane];
        float j2 = e2 + d[64 + lane];
        float j3 = e3 + d[96 + lane];

        float m = fmaxf(fmaxf(j0, j1), fmaxf(j2, j3));
#pragma unroll
        for (int dlt = 16; dlt > 0; dlt >>= 1)
            m = fmaxf(m, __shfl_xor_sync(0xffffffffu, m, dlt));
        float sm = __expf(j0 - m) + __expf(j1 - m) + __expf(j2 - m) + __expf(j3 - m);
#pragma unroll
        for (int dlt = 16; dlt > 0; dlt >>= 1)
            sm += __shfl_xor_sync(0xffffffffu, sm, dlt);
        float logZ = m + __logf(sm);

        if (lane == 0) lbp[u] = j0 - logZ;
        if (u < Uq) {
            int lbl = ys[b * Uq + u];
            int k = lbl >> 5, src = lbl & 31;
            float jv = (k == 0) ? j0 : (k == 1) ? j1 : (k == 2) ? j2 : j3;
            jv = __shfl_sync(0xffffffffu, jv, src);
            if (lane == 0) lyp[u] = jv - logZ;
        }
    }
}

// ---------------- RNN-T alpha recursion, chunked over t with gmem state ------------------
__device__ __forceinline__ float lsef(float a, float b)
{
    float mx = fmaxf(a, b), mn = fminf(a, b);
    return mx + __logf(1.f + __expf(mn - mx));
}

__global__ void __launch_bounds__(32) alpha_kernel(const int* __restrict__ xlen,
                                                   const int* __restrict__ ylen,
                                                   int t0, int tlen)
{
    const float BIG = -1e30f;
    int b = blockIdx.x;
    int lane = threadIdx.x;
    int tl = xlen[b], ul = ylen[b];
    if (t0 >= tl) return;
    const float* lbB = g_lb + (size_t)b * Tq * UP1;
    const float* lyB = g_ly + (size_t)b * Tq * Uq;
    int idx0 = lane * 4;

    float a[4];
    int tstart;
    if (t0 == 0) {
        float e[4];
#pragma unroll
        for (int j = 0; j < 4; j++) {
            int idx = idx0 + j;
            e[j] = (idx >= 1 && idx <= Uq) ? __ldg(&lyB[idx - 1]) : 0.f;
        }
        float sc[4];
        sc[0] = e[0]; sc[1] = sc[0] + e[1]; sc[2] = sc[1] + e[2]; sc[3] = sc[2] + e[3];
        float v = sc[3];
#pragma unroll
        for (int d = 1; d < 32; d <<= 1) {
            float t2 = __shfl_up_sync(0xffffffffu, v, d);
            if (lane >= d) v += t2;
        }
        float base = v - sc[3];
#pragma unroll
        for (int j = 0; j < 4; j++) a[j] = base + sc[j];
        tstart = 1;
    } else {
#pragma unroll
        for (int j = 0; j < 4; j++) a[j] = g_alpha[b * 128 + idx0 + j];
        tstart = t0;
    }

    int tend = (t0 + tlen < tl) ? (t0 + tlen) : tl;
    for (int t = tstart; t < tend; t++) {
        const float* lyr = lyB + (size_t)t * Uq;
        const float* lbr = lbB + (size_t)(t - 1) * UP1;
        float e[4], lbv[4];
#pragma unroll
        for (int j = 0; j < 4; j++) {
            int idx = idx0 + j;
            e[j]   = (idx >= 1 && idx <= Uq) ? __ldg(&lyr[idx - 1]) : 0.f;
            lbv[j] = (idx < UP1) ? __ldg(&lbr[idx]) : 0.f;
        }
        float sc[4];
        sc[0] = e[0]; sc[1] = sc[0] + e[1]; sc[2] = sc[1] + e[2]; sc[3] = sc[2] + e[3];
        float v = sc[3];
#pragma unroll
        for (int d = 1; d < 32; d <<= 1) {
            float t2 = __shfl_up_sync(0xffffffffu, v, d);
            if (lane >= d) v += t2;
        }
        float base = v - sc[3];
        float cj[4];
#pragma unroll
        for (int j = 0; j < 4; j++) cj[j] = base + sc[j];

        float x[4], m[4];
#pragma unroll
        for (int j = 0; j < 4; j++) {
            int idx = idx0 + j;
            x[j] = (idx < UP1) ? (a[j] + lbv[j] - cj[j]) : BIG;
        }
        m[0] = x[0];
        m[1] = lsef(m[0], x[1]);
        m[2] = lsef(m[1], x[2]);
        m[3] = lsef(m[2], x[3]);
        float z = m[3];
#pragma unroll
        for (int d = 1; d < 32; d <<= 1) {
            float t2 = __shfl_up_sync(0xffffffffu, z, d);
            if (lane >= d) z = lsef(z, t2);
        }
        float excl = __shfl_up_sync(0xffffffffu, z, 1);
        if (lane == 0) excl = BIG;
#pragma unroll
        for (int j = 0; j < 4; j++) a[j] = cj[j] + lsef(excl, m[j]);
    }

#pragma unroll
    for (int j = 0; j < 4; j++) g_alpha[b * 128 + idx0 + j] = a[j];

    if (tl <= t0 + tlen) {
        float sel = a[ul & 3];
        float aul = __shfl_sync(0xffffffffu, sel, ul >> 2);
        if (lane == 0)
            g_nll[b] = -(aul + __ldg(&lbB[(size_t)(tl - 1) * UP1 + ul]));
    }
}

__global__ void mean_kernel(float* __restrict__ out)
{
    float s = 0.f;
    for (int b = 0; b < Bq; b++) s += g_nll[b];
    out[0] = s / (float)Bq;
}

// ---------------- launch ----------------
static void launch_lstm16(cudaStream_t st, const float* Whh, const float* xp,
                          float* ho, int T)
{
    cudaLaunchConfig_t cfg = {};
    cfg.gridDim = dim3(16 * Bq, 1, 1);     // 8 clusters of 16 CTAs
    cfg.blockDim = dim3(320, 1, 1);
    cfg.dynamicSmemBytes = 0;
    cfg.stream = st;
    cudaLaunchAttribute attrs[1];
    attrs[0].id = cudaLaunchAttributeClusterDimension;
    attrs[0].val.clusterDim = {16, 1, 1};
    cfg.attrs = attrs;
    cfg.numAttrs = 1;
    cudaLaunchKernelEx(&cfg, lstm16_kernel, Whh, xp, ho, T);
}

extern "C" void kernel_launch(void* const* d_in, const int* in_sizes, int n_in,
                              void* d_out, int out_size)
{
    const float* xs    = (const float*)d_in[0];
    const int*   ys    = (const int*)  d_in[1];
    const int*   xlen  = (const int*)  d_in[2];
    const int*   ylen  = (const int*)  d_in[3];
    const float* eWih0 = (const float*)d_in[4];
    const float* eWhh0 = (const float*)d_in[5];
    const float* ebih0 = (const float*)d_in[6];
    const float* ebhh0 = (const float*)d_in[7];
    const float* eWih1 = (const float*)d_in[8];
    const float* eWhh1 = (const float*)d_in[9];
    const float* ebih1 = (const float*)d_in[10];
    const float* ebhh1 = (const float*)d_in[11];
    const float* eWo   = (const float*)d_in[12];
    const float* ebo   = (const float*)d_in[13];
    /* d_in[14] = embed (one-hot; folded into xpd gather) */
    const float* dWih  = (const float*)d_in[15];
    const float* dWhh  = (const float*)d_in[16];
    const float* dbih  = (const float*)d_in[17];
    const float* dbhh  = (const float*)d_in[18];
    const float* dWo   = (const float*)d_in[19];
    const float* dbo   = (const float*)d_in[20];
    float* out = (float*)d_out;

    float *xp0, *h0, *xp1, *h1, *enc, *xpd, *hd, *dec;
    cudaGetSymbolAddress((void**)&xp0, g_xp0);
    cudaGetSymbolAddress((void**)&h0,  g_h0);
    cudaGetSymbolAddress((void**)&xp1, g_xp1);
    cudaGetSymbolAddress((void**)&h1,  g_h1);
    cudaGetSymbolAddress((void**)&enc, g_enc);
    cudaGetSymbolAddress((void**)&xpd, g_xpd);
    cudaGetSymbolAddress((void**)&hd,  g_hd);
    cudaGetSymbolAddress((void**)&dec, g_dec);

    static cudaStream_t s1 = nullptr, s2 = nullptr;
    static cudaEvent_t Efork, Edec, EJ[NTC], Ea;
    static int inited = 0;
    if (!inited) {
        cudaStreamCreateWithFlags(&s1, cudaStreamNonBlocking);
        cudaStreamCreateWithFlags(&s2, cudaStreamNonBlocking);
        cudaEventCreateWithFlags(&Efork, cudaEventDisableTiming);
        cudaEventCreateWithFlags(&Edec, cudaEventDisableTiming);
        cudaEventCreateWithFlags(&Ea, cudaEventDisableTiming);
        for (int c = 0; c < NTC; c++)
            cudaEventCreateWithFlags(&EJ[c], cudaEventDisableTiming);
        cudaFuncSetAttribute(lstm16_kernel,
                             cudaFuncAttributeNonPortableClusterSizeAllowed, 1);
        inited = 1;
    }

    const int MT = Bq * Tq;       // 4000
    const int MU = Bq * UP1;      // 968
    cudaStream_t s0 = 0;

    cudaEventRecord(Efork, s0);
    cudaStreamWaitEvent(s1, Efork, 0);
    cudaStreamWaitEvent(s2, Efork, 0);

    // side stream: decoder branch (xpd -> dec LSTM -> dec proj)
    xpd_kernel<<<Bq * UP1, 256, 0, s1>>>(ys, dWih, dbih, dbhh);
    launch_lstm16(s1, dWhh, xpd, hd, DTq);
    gemm_nt<<<dim3(Vq / GBN, (MU + GBM - 1) / GBM), 256, 0, s1>>>(
        hd, dWo, dbo, nullptr, dec, MU, Vq, Hq);
    cudaEventRecord(Edec, s1);

    // main chain: encoder
    gemm_nt<<<dim3(G4 / GBN, (MT + GBM - 1) / GBM), 256, 0, s0>>>(
        xs, eWih0, ebih0, ebhh0, xp0, MT, G4, DIN);
    launch_lstm16(s0, eWhh0, xp0, h0, Tq);
    gemm_nt<<<dim3(G4 / GBN, (MT + GBM - 1) / GBM), 256, 0, s0>>>(
        h0, eWih1, ebih1, ebhh1, xp1, MT, G4, Hq);
    launch_lstm16(s0, eWhh1, xp1, h1, Tq);
    gemm_nt<<<dim3(Vq / GBN, (MT + GBM - 1) / GBM), 256, 0, s0>>>(
        h1, eWo, ebo, nullptr, enc, MT, Vq, Hq);

    // tail: joint chunks on s0, alpha chunks on s2 (overlapped)
    cudaStreamWaitEvent(s0, Edec, 0);
    for (int c = 0; c < NTC; c++) {
        int t0 = c * TCJ;
        joint_kernel<<<dim3((TCJ + 3) / 4, Bq), 128, 0, s0>>>(ys, t0);
        cudaEventRecord(EJ[c], s0);
        cudaStreamWaitEvent(s2, EJ[c], 0);
        alpha_kernel<<<Bq, 32, 0, s2>>>(xlen, ylen, t0, TCJ);
    }
    cudaEventRecord(Ea, s2);
    cudaStreamWaitEvent(s0, Ea, 0);
    mean_kernel<<<1, 1, 0, s0>>>(out);
}

// round 10
// speedup vs baseline: 1.2479x; 1.2479x over previous
#include <cuda_runtime.h>
#include <math.h>
#include <stdint.h>

#define Bq   8
#define Tq   500
#define Uq   120
#define UP1  121
#define Vq   128
#define Hq   320
#define G4   1280
#define DIN  80
#define VM1  127
#define DTq  121

#define NTC  4      // tail chunks (joint/alpha overlap)
#define TCJ  125    // t per tail chunk

// ---------------- static device scratch ----------------
__device__ float g_xp0[Bq * Tq * G4];
__device__ float g_h0 [Bq * Tq * Hq];
__device__ float g_xp1[Bq * Tq * G4];
__device__ float g_h1 [Bq * Tq * Hq];
__device__ float g_enc[Bq * Tq * Vq];
__device__ float g_xpd[Bq * UP1 * G4];
__device__ float g_hd [Bq * UP1 * Hq];
__device__ float g_dec[Bq * UP1 * Vq];
__device__ float g_lb [Bq * Tq * UP1];
__device__ float g_ly [Bq * Tq * Uq];
__device__ float g_nll[Bq];
__device__ float g_alpha[Bq * 128];

__device__ __forceinline__ float tanh_ap(float x)
{
    float y;
    asm("tanh.approx.f32 %0, %1;" : "=f"(y) : "f"(x));
    return y;
}
__device__ __forceinline__ float sig_ap(float x)
{
    return fmaf(0.5f, tanh_ap(0.5f * x), 0.5f);
}

// ---------------- tiled GEMM: C[M,N] = A[M,K] @ B[N,K]^T + b1 + b2 ----------------
#define GBM 128
#define GBN 64
#define GBK 16

__global__ void __launch_bounds__(256) gemm_nt(const float* __restrict__ A,
                                               const float* __restrict__ Bm,
                                               const float* __restrict__ b1,
                                               const float* __restrict__ b2,
                                               float* __restrict__ C,
                                               int M, int N, int K)
{
    __shared__ float As[GBK][GBM + 4];
    __shared__ float Bs[GBK][GBN + 4];
    int tid = threadIdx.x;
    int bm = blockIdx.y * GBM;
    int bn = blockIdx.x * GBN;
    int tx = tid & 15, ty = tid >> 4;

    float acc[8][4];
#pragma unroll
    for (int i = 0; i < 8; i++)
#pragma unroll
        for (int j = 0; j < 4; j++) acc[i][j] = 0.f;

    for (int k0 = 0; k0 < K; k0 += GBK) {
#pragma unroll
        for (int l = 0; l < 8; l++) {
            int idx = l * 256 + tid;
            int am = idx >> 4, ak = idx & 15;
            float v = 0.f;
            if (bm + am < M && k0 + ak < K) v = A[(size_t)(bm + am) * K + k0 + ak];
            As[ak][am] = v;
        }
#pragma unroll
        for (int l = 0; l < 4; l++) {
            int idx = l * 256 + tid;
            int bnn = idx >> 4, bk = idx & 15;
            float v = 0.f;
            if (bn + bnn < N && k0 + bk < K) v = Bm[(size_t)(bn + bnn) * K + k0 + bk];
            Bs[bk][bnn] = v;
        }
        __syncthreads();
#pragma unroll
        for (int k = 0; k < GBK; k++) {
            float4 a0 = *(const float4*)&As[k][ty * 8];
            float4 a1 = *(const float4*)&As[k][ty * 8 + 4];
            float4 bv = *(const float4*)&Bs[k][tx * 4];
            float af[8] = {a0.x, a0.y, a0.z, a0.w, a1.x, a1.y, a1.z, a1.w};
            float bf[4] = {bv.x, bv.y, bv.z, bv.w};
#pragma unroll
            for (int i = 0; i < 8; i++)
#pragma unroll
                for (int j = 0; j < 4; j++) acc[i][j] += af[i] * bf[j];
        }
        __syncthreads();
    }

    int n0 = bn + tx * 4;
    float bias[4];
#pragma unroll
    for (int j = 0; j < 4; j++)
        bias[j] = (b1 ? b1[n0 + j] : 0.f) + (b2 ? b2[n0 + j] : 0.f);

#pragma unroll
    for (int i = 0; i < 8; i++) {
        int m = bm + ty * 8 + i;
        if (m >= M) continue;
        float4 r;
        r.x = acc[i][0] + bias[0];
        r.y = acc[i][1] + bias[1];
        r.z = acc[i][2] + bias[2];
        r.w = acc[i][3] + bias[3];
        *(float4*)&C[(size_t)m * N + n0] = r;
    }
}

// ---------------- LSTM: 16-CTA cluster/batch, paired b64 st.async broadcast --------------
// 20 units/CTA; thread = (s = tid&15 K-slice of 20, rg = tid>>4 unit). Warp w holds units
// 2w,2w+1 (lanes 0-15 / 16-31). After activations, shfl_xor(16) exchanges partner h;
// even-rg threads send ONE st.async.b64 {h_rg, h_rg+1} to CTA s -> 160 transactions/CTA
// (halved mbarrier tx updates), no extra synchronization on the serial path.
__global__ void __launch_bounds__(320, 1)
lstm16_kernel(const float* __restrict__ Whh, const float* __restrict__ xproj,
              float* __restrict__ hout, int T)
{
    __shared__ __align__(16) float hbuf[2][Hq];          // buffer stride 1280 B
    __shared__ __align__(8) unsigned long long mbars[2];

    unsigned rank;
    asm("mov.u32 %0, %%cluster_ctarank;" : "=r"(rank));
    int batch = blockIdx.x >> 4;

    int tid = threadIdx.x;
    int s   = tid & 15;           // K-slice (20 wide)
    int rg  = tid >> 4;           // local unit 0..19
    int unit = (int)rank * 20 + rg;

    // register-resident weights: 4 gates x 20 K = 80 floats as 40 u64
    unsigned long long w[4][10];
#pragma unroll
    for (int r = 0; r < 4; r++) {
        const ulonglong2* p = reinterpret_cast<const ulonglong2*>(
            Whh + (size_t)(r * Hq + unit) * Hq + s * 20);
#pragma unroll
        for (int i = 0; i < 5; i++) {
            ulonglong2 u = p[i];
            w[r][2 * i] = u.x; w[r][2 * i + 1] = u.y;
        }
    }

    hbuf[0][tid] = 0.f;
    float c = 0.f;

    unsigned mb_local = (unsigned)__cvta_generic_to_shared(&mbars[0]);
    if (tid == 0) {
        asm volatile("mbarrier.init.shared.b64 [%0], 1;" :: "r"(mb_local) : "memory");
        asm volatile("mbarrier.init.shared.b64 [%0], 1;" :: "r"(mb_local + 8) : "memory");
    }

    const float* xpb = xproj + ((size_t)batch * T) * G4 + unit;
    float xg0 = 0.f, xg1 = 0.f, xg2 = 0.f, xg3 = 0.f;
    if (s == 0) {
        xg0 = __ldg(xpb);
        xg1 = __ldg(xpb + Hq);
        xg2 = __ldg(xpb + 2 * Hq);
        xg3 = __ldg(xpb + 3 * Hq);
    }

    // even-rg threads send the pair {h_rg, h_rg+1} (8 bytes) to peer CTA 's'
    unsigned h_local = (unsigned)__cvta_generic_to_shared(&hbuf[0][0])
                     + (rank * 20u + (unsigned)rg) * 4u;
    unsigned rh, rm;
    asm("mapa.shared::cluster.u32 %0, %1, %2;" : "=r"(rh) : "r"(h_local), "r"(s));
    asm("mapa.shared::cluster.u32 %0, %1, %2;" : "=r"(rm) : "r"(mb_local), "r"(s));

    __syncthreads();
    asm volatile("barrier.cluster.arrive.aligned;" ::: "memory");
    asm volatile("barrier.cluster.wait.aligned;" ::: "memory");

    unsigned ph0 = 0, ph1 = 0;

    for (int t = 0; t < T; t++) {
        int cur = t & 1, nxt = cur ^ 1;
        int not_last = (t + 1 < T);

        if (not_last && tid == 0)
            asm volatile("mbarrier.arrive.expect_tx.shared.b64 _, [%0], 1280;"
                         :: "r"(mb_local + (unsigned)nxt * 8) : "memory");

        // matvec: 4 gate rows x 20 K, f32x2 packed
        const ulonglong2* h2 =
            reinterpret_cast<const ulonglong2*>(&hbuf[cur][s * 20]);
        unsigned long long a0 = 0ULL, a1 = 0ULL, a2 = 0ULL, a3 = 0ULL;
#pragma unroll
        for (int i = 0; i < 5; i++) {
            ulonglong2 hv = h2[i];
            asm("fma.rn.f32x2 %0, %1, %2, %0;" : "+l"(a0) : "l"(w[0][2*i]),   "l"(hv.x));
            asm("fma.rn.f32x2 %0, %1, %2, %0;" : "+l"(a1) : "l"(w[1][2*i]),   "l"(hv.x));
            asm("fma.rn.f32x2 %0, %1, %2, %0;" : "+l"(a2) : "l"(w[2][2*i]),   "l"(hv.x));
            asm("fma.rn.f32x2 %0, %1, %2, %0;" : "+l"(a3) : "l"(w[3][2*i]),   "l"(hv.x));
            asm("fma.rn.f32x2 %0, %1, %2, %0;" : "+l"(a0) : "l"(w[0][2*i+1]), "l"(hv.y));
            asm("fma.rn.f32x2 %0, %1, %2, %0;" : "+l"(a1) : "l"(w[1][2*i+1]), "l"(hv.y));
            asm("fma.rn.f32x2 %0, %1, %2, %0;" : "+l"(a2) : "l"(w[2][2*i+1]), "l"(hv.y));
            asm("fma.rn.f32x2 %0, %1, %2, %0;" : "+l"(a3) : "l"(w[3][2*i+1]), "l"(hv.y));
        }
        float g0, g1, g2, g3;
        {
            unsigned lo, hi;
            asm("mov.b64 {%0,%1}, %2;" : "=r"(lo), "=r"(hi) : "l"(a0));
            g0 = __uint_as_float(lo) + __uint_as_float(hi);
            asm("mov.b64 {%0,%1}, %2;" : "=r"(lo), "=r"(hi) : "l"(a1));
            g1 = __uint_as_float(lo) + __uint_as_float(hi);
            asm("mov.b64 {%0,%1}, %2;" : "=r"(lo), "=r"(hi) : "l"(a2));
            g2 = __uint_as_float(lo) + __uint_as_float(hi);
            asm("mov.b64 {%0,%1}, %2;" : "=r"(lo), "=r"(hi) : "l"(a3));
            g3 = __uint_as_float(lo) + __uint_as_float(hi);
        }
        if (s == 0) { g0 += xg0; g1 += xg1; g2 += xg2; g3 += xg3; }

        // prefetch next-step xproj
        if (s == 0 && not_last) {
            const float* xq = xpb + (size_t)(t + 1) * G4;
            xg0 = __ldg(xq);
            xg1 = __ldg(xq + Hq);
            xg2 = __ldg(xq + 2 * Hq);
            xg3 = __ldg(xq + 3 * Hq);
        }

        // butterfly over the 16 slice lanes
#pragma unroll
        for (int d = 1; d < 16; d <<= 1) {
            g0 += __shfl_xor_sync(0xffffffffu, g0, d);
            g1 += __shfl_xor_sync(0xffffffffu, g1, d);
            g2 += __shfl_xor_sync(0xffffffffu, g2, d);
            g3 += __shfl_xor_sync(0xffffffffu, g3, d);
        }

        // fast activations: tanh.approx; sigmoid(x) = 0.5*tanh(x/2)+0.5
        float i_ = sig_ap(g0);
        float f_ = sig_ap(g1);
        float gg = tanh_ap(g2);
        float o_ = sig_ap(g3);
        c = f_ * c + i_ * gg;
        float h = o_ * tanh_ap(c);

        if (s == 0)
            hout[((size_t)batch * T + t) * Hq + unit] = h;

        // partner exchange: warp holds units rg (lanes 0-15) and rg+1 (lanes 16-31)
        float hp = __shfl_xor_sync(0xffffffffu, h, 16);

        if (not_last) {
            if ((rg & 1) == 0) {
                unsigned long long pk;
                asm("mov.b64 %0, {%1, %2};" : "=l"(pk)
                    : "r"(__float_as_uint(h)), "r"(__float_as_uint(hp)));
                asm volatile(
                    "st.async.shared::cluster.mbarrier::complete_tx::bytes.b64 "
                    "[%0], %1, [%2];"
                    :: "r"(rh + (unsigned)nxt * 1280u), "l"(pk),
                       "r"(rm + (unsigned)nxt * 8u) : "memory");
            }
            unsigned par = nxt ? ph1 : ph0;
            unsigned mb  = mb_local + (unsigned)nxt * 8;
            asm volatile(
                "{\n\t.reg .pred P;\n\t"
                "WL_%=:\n\t"
                "mbarrier.try_wait.parity.acquire.cta.shared::cta.b64 P, [%0], %1, 0x989680;\n\t"
                "@!P bra WL_%=;\n\t}"
                :: "r"(mb), "r"(par) : "memory");
            if (nxt) ph1 ^= 1; else ph0 ^= 1;
        }
    }
}

// ---------------- decoder xproj via embedding gather (one-hot rows) ----------------
__global__ void __launch_bounds__(256) xpd_kernel(const int* __restrict__ ys,
                                                  const float* __restrict__ Wih,
                                                  const float* __restrict__ bih,
                                                  const float* __restrict__ bhh)
{
    int b = blockIdx.x / UP1, u = blockIdx.x % UP1;
    int id = (u == 0) ? 0 : ys[b * Uq + u - 1];
    float* dst = g_xpd + ((size_t)b * UP1 + u) * G4;
    for (int g = threadIdx.x; g < G4; g += 256) {
        float v = bih[g] + bhh[g];
        if (id > 0) v += Wih[(size_t)g * VM1 + (id - 1)];
        dst[g] = v;
    }
}

// ---------------- joint + log-softmax -> lb/ly, per t-chunk ----------------
__global__ void __launch_bounds__(128) joint_kernel(const int* __restrict__ ys, int t0)
{
    int b = blockIdx.y;
    int t = t0 + blockIdx.x * 4 + (threadIdx.x >> 5);
    if (t >= t0 + TCJ || t >= Tq) return;
    int lane = threadIdx.x & 31;

    const float* e = g_enc + ((size_t)b * Tq + t) * Vq;
    float e0 = e[lane], e1 = e[32 + lane], e2 = e[64 + lane], e3 = e[96 + lane];
    float* lbp = g_lb + ((size_t)b * Tq + t) * UP1;
    float* lyp = g_ly + ((size_t)b * Tq + t) * Uq;

    for (int u = 0; u < UP1; u++) {
        const float* d = g_dec + ((size_t)b * UP1 + u) * Vq;
        float j0 = e0 + d[lane];
        float j1 = e1 + d[32 + lane];
        float j2 = e2 + d[64 + lane];
        float j3 = e3 + d[96 + lane];

        float m = fmaxf(fmaxf(j0, j1), fmaxf(j2, j3));
#pragma unroll
        for (int dlt = 16; dlt > 0; dlt >>= 1)
            m = fmaxf(m, __shfl_xor_sync(0xffffffffu, m, dlt));
        float sm = __expf(j0 - m) + __expf(j1 - m) + __expf(j2 - m) + __expf(j3 - m);
#pragma unroll
        for (int dlt = 16; dlt > 0; dlt >>= 1)
            sm += __shfl_xor_sync(0xffffffffu, sm, dlt);
        float logZ = m + __logf(sm);

        if (lane == 0) lbp[u] = j0 - logZ;
        if (u < Uq) {
            int lbl = ys[b * Uq + u];
            int k = lbl >> 5, src = lbl & 31;
            float jv = (k == 0) ? j0 : (k == 1) ? j1 : (k == 2) ? j2 : j3;
            jv = __shfl_sync(0xffffffffu, jv, src);
            if (lane == 0) lyp[u] = jv - logZ;
        }
    }
}

// ---------------- RNN-T alpha recursion, chunked over t with gmem state ------------------
__device__ __forceinline__ float lsef(float a, float b)
{
    float mx = fmaxf(a, b), mn = fminf(a, b);
    return mx + __logf(1.f + __expf(mn - mx));
}

__global__ void __launch_bounds__(32) alpha_kernel(const int* __restrict__ xlen,
                                                   const int* __restrict__ ylen,
                                                   int t0, int tlen)
{
    const float BIG = -1e30f;
    int b = blockIdx.x;
    int lane = threadIdx.x;
    int tl = xlen[b], ul = ylen[b];
    if (t0 >= tl) return;
    const float* lbB = g_lb + (size_t)b * Tq * UP1;
    const float* lyB = g_ly + (size_t)b * Tq * Uq;
    int idx0 = lane * 4;

    float a[4];
    int tstart;
    if (t0 == 0) {
        float e[4];
#pragma unroll
        for (int j = 0; j < 4; j++) {
            int idx = idx0 + j;
            e[j] = (idx >= 1 && idx <= Uq) ? __ldg(&lyB[idx - 1]) : 0.f;
        }
        float sc[4];
        sc[0] = e[0]; sc[1] = sc[0] + e[1]; sc[2] = sc[1] + e[2]; sc[3] = sc[2] + e[3];
        float v = sc[3];
#pragma unroll
        for (int d = 1; d < 32; d <<= 1) {
            float t2 = __shfl_up_sync(0xffffffffu, v, d);
            if (lane >= d) v += t2;
        }
        float base = v - sc[3];
#pragma unroll
        for (int j = 0; j < 4; j++) a[j] = base + sc[j];
        tstart = 1;
    } else {
#pragma unroll
        for (int j = 0; j < 4; j++) a[j] = g_alpha[b * 128 + idx0 + j];
        tstart = t0;
    }

    int tend = (t0 + tlen < tl) ? (t0 + tlen) : tl;
    for (int t = tstart; t < tend; t++) {
        const float* lyr = lyB + (size_t)t * Uq;
        const float* lbr = lbB + (size_t)(t - 1) * UP1;
        float e[4], lbv[4];
#pragma unroll
        for (int j = 0; j < 4; j++) {
            int idx = idx0 + j;
            e[j]   = (idx >= 1 && idx <= Uq) ? __ldg(&lyr[idx - 1]) : 0.f;
            lbv[j] = (idx < UP1) ? __ldg(&lbr[idx]) : 0.f;
        }
        float sc[4];
        sc[0] = e[0]; sc[1] = sc[0] + e[1]; sc[2] = sc[1] + e[2]; sc[3] = sc[2] + e[3];
        float v = sc[3];
#pragma unroll
        for (int d = 1; d < 32; d <<= 1) {
            float t2 = __shfl_up_sync(0xffffffffu, v, d);
            if (lane >= d) v += t2;
        }
        float base = v - sc[3];
        float cj[4];
#pragma unroll
        for (int j = 0; j < 4; j++) cj[j] = base + sc[j];

        float x[4], m[4];
#pragma unroll
        for (int j = 0; j < 4; j++) {
            int idx = idx0 + j;
            x[j] = (idx < UP1) ? (a[j] + lbv[j] - cj[j]) : BIG;
        }
        m[0] = x[0];
        m[1] = lsef(m[0], x[1]);
        m[2] = lsef(m[1], x[2]);
        m[3] = lsef(m[2], x[3]);
        float z = m[3];
#pragma unroll
        for (int d = 1; d < 32; d <<= 1) {
            float t2 = __shfl_up_sync(0xffffffffu, z, d);
            if (lane >= d) z = lsef(z, t2);
        }
        float excl = __shfl_up_sync(0xffffffffu, z, 1);
        if (lane == 0) excl = BIG;
#pragma unroll
        for (int j = 0; j < 4; j++) a[j] = cj[j] + lsef(excl, m[j]);
    }

#pragma unroll
    for (int j = 0; j < 4; j++) g_alpha[b * 128 + idx0 + j] = a[j];

    if (tl <= t0 + tlen) {
        float sel = a[ul & 3];
        float aul = __shfl_sync(0xffffffffu, sel, ul >> 2);
        if (lane == 0)
            g_nll[b] = -(aul + __ldg(&lbB[(size_t)(tl - 1) * UP1 + ul]));
    }
}

__global__ void zero_nll_kernel()
{
    if (threadIdx.x < Bq) g_nll[threadIdx.x] = 0.f;
}

__global__ void mean_kernel(float* __restrict__ out)
{
    float s = 0.f;
    for (int b = 0; b < Bq; b++) s += g_nll[b];
    out[0] = s / (float)Bq;
}

// ---------------- launch ----------------
static void launch_lstm16(cudaStream_t st, const float* Whh, const float* xp,
                          float* ho, int T)
{
    cudaLaunchConfig_t cfg = {};
    cfg.gridDim = dim3(16 * Bq, 1, 1);     // 8 clusters of 16 CTAs
    cfg.blockDim = dim3(320, 1, 1);
    cfg.dynamicSmemBytes = 0;
    cfg.stream = st;
    cudaLaunchAttribute attrs[1];
    attrs[0].id = cudaLaunchAttributeClusterDimension;
    attrs[0].val.clusterDim = {16, 1, 1};
    cfg.attrs = attrs;
    cfg.numAttrs = 1;
    cudaLaunchKernelEx(&cfg, lstm16_kernel, Whh, xp, ho, T);
}

extern "C" void kernel_launch(void* const* d_in, const int* in_sizes, int n_in,
                              void* d_out, int out_size)
{
    const float* xs    = (const float*)d_in[0];
    const int*   ys    = (const int*)  d_in[1];
    const int*   xlen  = (const int*)  d_in[2];
    const int*   ylen  = (const int*)  d_in[3];
    const float* eWih0 = (const float*)d_in[4];
    const float* eWhh0 = (const float*)d_in[5];
    const float* ebih0 = (const float*)d_in[6];
    const float* ebhh0 = (const float*)d_in[7];
    const float* eWih1 = (const float*)d_in[8];
    const float* eWhh1 = (const float*)d_in[9];
    const float* ebih1 = (const float*)d_in[10];
    const float* ebhh1 = (const float*)d_in[11];
    const float* eWo   = (const float*)d_in[12];
    const float* ebo   = (const float*)d_in[13];
    /* d_in[14] = embed (one-hot; folded into xpd gather) */
    const float* dWih  = (const float*)d_in[15];
    const float* dWhh  = (const float*)d_in[16];
    const float* dbih  = (const float*)d_in[17];
    const float* dbhh  = (const float*)d_in[18];
    const float* dWo   = (const float*)d_in[19];
    const float* dbo   = (const float*)d_in[20];
    float* out = (float*)d_out;

    float *xp0, *h0, *xp1, *h1, *enc, *xpd, *hd, *dec;
    cudaGetSymbolAddress((void**)&xp0, g_xp0);
    cudaGetSymbolAddress((void**)&h0,  g_h0);
    cudaGetSymbolAddress((void**)&xp1, g_xp1);
    cudaGetSymbolAddress((void**)&h1,  g_h1);
    cudaGetSymbolAddress((void**)&enc, g_enc);
    cudaGetSymbolAddress((void**)&xpd, g_xpd);
    cudaGetSymbolAddress((void**)&hd,  g_hd);
    cudaGetSymbolAddress((void**)&dec, g_dec);

    static cudaStream_t s1 = nullptr, s2 = nullptr;
    static cudaEvent_t Efork, Edec, EJ[NTC], Ea;
    static int inited = 0;
    if (!inited) {
        cudaStreamCreateWithFlags(&s1, cudaStreamNonBlocking);
        cudaStreamCreateWithFlags(&s2, cudaStreamNonBlocking);
        cudaEventCreateWithFlags(&Efork, cudaEventDisableTiming);
        cudaEventCreateWithFlags(&Edec, cudaEventDisableTiming);
        cudaEventCreateWithFlags(&Ea, cudaEventDisableTiming);
        for (int c = 0; c < NTC; c++)
            cudaEventCreateWithFlags(&EJ[c], cudaEventDisableTiming);
        cudaFuncSetAttribute(lstm16_kernel,
                             cudaFuncAttributeNonPortableClusterSizeAllowed, 1);
        inited = 1;
    }

    const int MT = Bq * Tq;       // 4000
    const int MU = Bq * UP1;      // 968
    cudaStream_t s0 = 0;

    cudaEventRecord(Efork, s0);
    cudaStreamWaitEvent(s1, Efork, 0);
    cudaStreamWaitEvent(s2, Efork, 0);

    // launch index 0 (shifts enc0 lstm to index 5 so ncu -s 5 captures it)
    zero_nll_kernel<<<1, 32, 0, s2>>>();

    // side stream: decoder branch (xpd -> dec LSTM -> dec proj)
    xpd_kernel<<<Bq * UP1, 256, 0, s1>>>(ys, dWih, dbih, dbhh);
    launch_lstm16(s1, dWhh, xpd, hd, DTq);
    gemm_nt<<<dim3(Vq / GBN, (MU + GBM - 1) / GBM), 256, 0, s1>>>(
        hd, dWo, dbo, nullptr, dec, MU, Vq, Hq);
    cudaEventRecord(Edec, s1);

    // main chain: encoder
    gemm_nt<<<dim3(G4 / GBN, (MT + GBM - 1) / GBM), 256, 0, s0>>>(
        xs, eWih0, ebih0, ebhh0, xp0, MT, G4, DIN);
    launch_lstm16(s0, eWhh0, xp0, h0, Tq);
    gemm_nt<<<dim3(G4 / GBN, (MT + GBM - 1) / GBM), 256, 0, s0>>>(
        h0, eWih1, ebih1, ebhh1, xp1, MT, G4, Hq);
    launch_lstm16(s0, eWhh1, xp1, h1, Tq);
    gemm_nt<<<dim3(Vq / GBN, (MT + GBM - 1) / GBM), 256, 0, s0>>>(
        h1, eWo, ebo, nullptr, enc, MT, Vq, Hq);

    // tail: joint chunks on s0, alpha chunks on s2 (overlapped)
    cudaStreamWaitEvent(s0, Edec, 0);
    for (int c = 0; c < NTC; c++) {
        int t0 = c * TCJ;
        joint_kernel<<<dim3((TCJ + 3) / 4, Bq), 128, 0, s0>>>(ys, t0);
        cudaEventRecord(EJ[c], s0);
        cudaStreamWaitEvent(s2, EJ[c], 0);
        alpha_kernel<<<Bq, 32, 0, s2>>>(xlen, ylen, t0, TCJ);
    }
    cudaEventRecord(Ea, s2);
    cudaStreamWaitEvent(s0, Ea, 0);
    mean_kernel<<<1, 1, 0, s0>>>(out);
}

// round 11
// speedup vs baseline: 1.2490x; 1.0009x over previous
#include <cuda_runtime.h>
#include <math.h>
#include <stdint.h>

#define Bq   8
#define Tq   500
#define Uq   120
#define UP1  121
#define Vq   128
#define Hq   320
#define G4   1280
#define DIN  80
#define VM1  127
#define DTq  121

#define NTC  4      // tail chunks (joint/alpha overlap)
#define TCJ  125    // t per tail chunk

// ---------------- static device scratch ----------------
__device__ float g_xp0[Bq * Tq * G4];
__device__ float g_h0 [Bq * Tq * Hq];
__device__ float g_xp1[Bq * Tq * G4];
__device__ float g_h1 [Bq * Tq * Hq];
__device__ float g_enc[Bq * Tq * Vq];
__device__ float g_xpd[Bq * UP1 * G4];
__device__ float g_hd [Bq * UP1 * Hq];
__device__ float g_dec[Bq * UP1 * Vq];
__device__ float g_lb [Bq * Tq * UP1];
__device__ float g_ly [Bq * Tq * Uq];
__device__ float g_nll[Bq];
__device__ float g_alpha[Bq * 128];

__device__ __forceinline__ float tanh_ap(float x)
{
    float y;
    asm("tanh.approx.f32 %0, %1;" : "=f"(y) : "f"(x));
    return y;
}
__device__ __forceinline__ float sig_ap(float x)
{
    return fmaf(0.5f, tanh_ap(0.5f * x), 0.5f);
}

// ---------------- tiled GEMM: C[M,N] = A[M,K] @ B[N,K]^T + b1 + b2 ----------------
#define GBM 128
#define GBN 64
#define GBK 16

__global__ void __launch_bounds__(256) gemm_nt(const float* __restrict__ A,
                                               const float* __restrict__ Bm,
                                               const float* __restrict__ b1,
                                               const float* __restrict__ b2,
                                               float* __restrict__ C,
                                               int M, int N, int K)
{
    __shared__ float As[GBK][GBM + 4];
    __shared__ float Bs[GBK][GBN + 4];
    int tid = threadIdx.x;
    int bm = blockIdx.y * GBM;
    int bn = blockIdx.x * GBN;
    int tx = tid & 15, ty = tid >> 4;

    float acc[8][4];
#pragma unroll
    for (int i = 0; i < 8; i++)
#pragma unroll
        for (int j = 0; j < 4; j++) acc[i][j] = 0.f;

    for (int k0 = 0; k0 < K; k0 += GBK) {
#pragma unroll
        for (int l = 0; l < 8; l++) {
            int idx = l * 256 + tid;
            int am = idx >> 4, ak = idx & 15;
            float v = 0.f;
            if (bm + am < M && k0 + ak < K) v = A[(size_t)(bm + am) * K + k0 + ak];
            As[ak][am] = v;
        }
#pragma unroll
        for (int l = 0; l < 4; l++) {
            int idx = l * 256 + tid;
            int bnn = idx >> 4, bk = idx & 15;
            float v = 0.f;
            if (bn + bnn < N && k0 + bk < K) v = Bm[(size_t)(bn + bnn) * K + k0 + bk];
            Bs[bk][bnn] = v;
        }
        __syncthreads();
#pragma unroll
        for (int k = 0; k < GBK; k++) {
            float4 a0 = *(const float4*)&As[k][ty * 8];
            float4 a1 = *(const float4*)&As[k][ty * 8 + 4];
            float4 bv = *(const float4*)&Bs[k][tx * 4];
            float af[8] = {a0.x, a0.y, a0.z, a0.w, a1.x, a1.y, a1.z, a1.w};
            float bf[4] = {bv.x, bv.y, bv.z, bv.w};
#pragma unroll
            for (int i = 0; i < 8; i++)
#pragma unroll
                for (int j = 0; j < 4; j++) acc[i][j] += af[i] * bf[j];
        }
        __syncthreads();
    }

    int n0 = bn + tx * 4;
    float bias[4];
#pragma unroll
    for (int j = 0; j < 4; j++)
        bias[j] = (b1 ? b1[n0 + j] : 0.f) + (b2 ? b2[n0 + j] : 0.f);

#pragma unroll
    for (int i = 0; i < 8; i++) {
        int m = bm + ty * 8 + i;
        if (m >= M) continue;
        float4 r;
        r.x = acc[i][0] + bias[0];
        r.y = acc[i][1] + bias[1];
        r.z = acc[i][2] + bias[2];
        r.w = acc[i][3] + bias[3];
        *(float4*)&C[(size_t)m * N + n0] = r;
    }
}

// ---------------- LSTM: 16-CTA cluster/batch, paired b64 st.async broadcast --------------
// 20 units/CTA; thread = (s = tid&15 K-slice of 20, rg = tid>>4 unit). Warp w holds units
// 2w,2w+1 (lanes 0-15 / 16-31). After activations, shfl_xor(16) exchanges partner h;
// even-rg threads send ONE st.async.b64 {h_rg, h_rg+1} to CTA s -> 160 transactions/CTA
// (halved mbarrier tx updates), no extra synchronization on the serial path.
__global__ void __launch_bounds__(320, 1)
lstm16_kernel(const float* __restrict__ Whh, const float* __restrict__ xproj,
              float* __restrict__ hout, int T)
{
    __shared__ __align__(16) float hbuf[2][Hq];          // buffer stride 1280 B
    __shared__ __align__(8) unsigned long long mbars[2];

    unsigned rank;
    asm("mov.u32 %0, %%cluster_ctarank;" : "=r"(rank));
    int batch = blockIdx.x >> 4;

    int tid = threadIdx.x;
    int s   = tid & 15;           // K-slice (20 wide)
    int rg  = tid >> 4;           // local unit 0..19
    int unit = (int)rank * 20 + rg;

    // register-resident weights: 4 gates x 20 K = 80 floats as 40 u64
    unsigned long long w[4][10];
#pragma unroll
    for (int r = 0; r < 4; r++) {
        const ulonglong2* p = reinterpret_cast<const ulonglong2*>(
            Whh + (size_t)(r * Hq + unit) * Hq + s * 20);
#pragma unroll
        for (int i = 0; i < 5; i++) {
            ulonglong2 u = p[i];
            w[r][2 * i] = u.x; w[r][2 * i + 1] = u.y;
        }
    }

    hbuf[0][tid] = 0.f;
    float c = 0.f;

    unsigned mb_local = (unsigned)__cvta_generic_to_shared(&mbars[0]);
    if (tid == 0) {
        asm volatile("mbarrier.init.shared.b64 [%0], 1;" :: "r"(mb_local) : "memory");
        asm volatile("mbarrier.init.shared.b64 [%0], 1;" :: "r"(mb_local + 8) : "memory");
    }

    const float* xpb = xproj + ((size_t)batch * T) * G4 + unit;
    float xg0 = 0.f, xg1 = 0.f, xg2 = 0.f, xg3 = 0.f;
    if (s == 0) {
        xg0 = __ldg(xpb);
        xg1 = __ldg(xpb + Hq);
        xg2 = __ldg(xpb + 2 * Hq);
        xg3 = __ldg(xpb + 3 * Hq);
    }

    // even-rg threads send the pair {h_rg, h_rg+1} (8 bytes) to peer CTA 's'
    unsigned h_local = (unsigned)__cvta_generic_to_shared(&hbuf[0][0])
                     + (rank * 20u + (unsigned)rg) * 4u;
    unsigned rh, rm;
    asm("mapa.shared::cluster.u32 %0, %1, %2;" : "=r"(rh) : "r"(h_local), "r"(s));
    asm("mapa.shared::cluster.u32 %0, %1, %2;" : "=r"(rm) : "r"(mb_local), "r"(s));

    __syncthreads();
    asm volatile("barrier.cluster.arrive.aligned;" ::: "memory");
    asm volatile("barrier.cluster.wait.aligned;" ::: "memory");

    unsigned ph0 = 0, ph1 = 0;

    for (int t = 0; t < T; t++) {
        int cur = t & 1, nxt = cur ^ 1;
        int not_last = (t + 1 < T);

        if (not_last && tid == 0)
            asm volatile("mbarrier.arrive.expect_tx.shared.b64 _, [%0], 1280;"
                         :: "r"(mb_local + (unsigned)nxt * 8) : "memory");

        // matvec: 4 gate rows x 20 K, f32x2 packed
        const ulonglong2* h2 =
            reinterpret_cast<const ulonglong2*>(&hbuf[cur][s * 20]);
        unsigned long long a0 = 0ULL, a1 = 0ULL, a2 = 0ULL, a3 = 0ULL;
#pragma unroll
        for (int i = 0; i < 5; i++) {
            ulonglong2 hv = h2[i];
            asm("fma.rn.f32x2 %0, %1, %2, %0;" : "+l"(a0) : "l"(w[0][2*i]),   "l"(hv.x));
            asm("fma.rn.f32x2 %0, %1, %2, %0;" : "+l"(a1) : "l"(w[1][2*i]),   "l"(hv.x));
            asm("fma.rn.f32x2 %0, %1, %2, %0;" : "+l"(a2) : "l"(w[2][2*i]),   "l"(hv.x));
            asm("fma.rn.f32x2 %0, %1, %2, %0;" : "+l"(a3) : "l"(w[3][2*i]),   "l"(hv.x));
            asm("fma.rn.f32x2 %0, %1, %2, %0;" : "+l"(a0) : "l"(w[0][2*i+1]), "l"(hv.y));
            asm("fma.rn.f32x2 %0, %1, %2, %0;" : "+l"(a1) : "l"(w[1][2*i+1]), "l"(hv.y));
            asm("fma.rn.f32x2 %0, %1, %2, %0;" : "+l"(a2) : "l"(w[2][2*i+1]), "l"(hv.y));
            asm("fma.rn.f32x2 %0, %1, %2, %0;" : "+l"(a3) : "l"(w[3][2*i+1]), "l"(hv.y));
        }
        float g0, g1, g2, g3;
        {
            unsigned lo, hi;
            asm("mov.b64 {%0,%1}, %2;" : "=r"(lo), "=r"(hi) : "l"(a0));
            g0 = __uint_as_float(lo) + __uint_as_float(hi);
            asm("mov.b64 {%0,%1}, %2;" : "=r"(lo), "=r"(hi) : "l"(a1));
            g1 = __uint_as_float(lo) + __uint_as_float(hi);
            asm("mov.b64 {%0,%1}, %2;" : "=r"(lo), "=r"(hi) : "l"(a2));
            g2 = __uint_as_float(lo) + __uint_as_float(hi);
            asm("mov.b64 {%0,%1}, %2;" : "=r"(lo), "=r"(hi) : "l"(a3));
            g3 = __uint_as_float(lo) + __uint_as_float(hi);
        }
        if (s == 0) { g0 += xg0; g1 += xg1; g2 += xg2; g3 += xg3; }

        // prefetch next-step xproj
        if (s == 0 && not_last) {
            const float* xq = xpb + (size_t)(t + 1) * G4;
            xg0 = __ldg(xq);
            xg1 = __ldg(xq + Hq);
            xg2 = __ldg(xq + 2 * Hq);
            xg3 = __ldg(xq + 3 * Hq);
        }

        // butterfly over the 16 slice lanes
#pragma unroll
        for (int d = 1; d < 16; d <<= 1) {
            g0 += __shfl_xor_sync(0xffffffffu, g0, d);
            g1 += __shfl_xor_sync(0xffffffffu, g1, d);
            g2 += __shfl_xor_sync(0xffffffffu, g2, d);
            g3 += __shfl_xor_sync(0xffffffffu, g3, d);
        }

        // fast activations: tanh.approx; sigmoid(x) = 0.5*tanh(x/2)+0.5
        float i_ = sig_ap(g0);
        float f_ = sig_ap(g1);
        float gg = tanh_ap(g2);
        float o_ = sig_ap(g3);
        c = f_ * c + i_ * gg;
        float h = o_ * tanh_ap(c);

        if (s == 0)
            hout[((size_t)batch * T + t) * Hq + unit] = h;

        // partner exchange: warp holds units rg (lanes 0-15) and rg+1 (lanes 16-31)
        float hp = __shfl_xor_sync(0xffffffffu, h, 16);

        if (not_last) {
            if ((rg & 1) == 0) {
                unsigned long long pk;
                asm("mov.b64 %0, {%1, %2};" : "=l"(pk)
                    : "r"(__float_as_uint(h)), "r"(__float_as_uint(hp)));
                asm volatile(
                    "st.async.shared::cluster.mbarrier::complete_tx::bytes.b64 "
                    "[%0], %1, [%2];"
                    :: "r"(rh + (unsigned)nxt * 1280u), "l"(pk),
                       "r"(rm + (unsigned)nxt * 8u) : "memory");
            }
            unsigned par = nxt ? ph1 : ph0;
            unsigned mb  = mb_local + (unsigned)nxt * 8;
            asm volatile(
                "{\n\t.reg .pred P;\n\t"
                "WL_%=:\n\t"
                "mbarrier.try_wait.parity.acquire.cta.shared::cta.b64 P, [%0], %1, 0x989680;\n\t"
                "@!P bra WL_%=;\n\t}"
                :: "r"(mb), "r"(par) : "memory");
            if (nxt) ph1 ^= 1; else ph0 ^= 1;
        }
    }
}

// ---------------- decoder xproj via embedding gather (one-hot rows) ----------------
__global__ void __launch_bounds__(256) xpd_kernel(const int* __restrict__ ys,
                                                  const float* __restrict__ Wih,
                                                  const float* __restrict__ bih,
                                                  const float* __restrict__ bhh)
{
    int b = blockIdx.x / UP1, u = blockIdx.x % UP1;
    int id = (u == 0) ? 0 : ys[b * Uq + u - 1];
    float* dst = g_xpd + ((size_t)b * UP1 + u) * G4;
    for (int g = threadIdx.x; g < G4; g += 256) {
        float v = bih[g] + bhh[g];
        if (id > 0) v += Wih[(size_t)g * VM1 + (id - 1)];
        dst[g] = v;
    }
}

// ---------------- joint + log-softmax -> lb/ly, per t-chunk ----------------
__global__ void __launch_bounds__(128) joint_kernel(const int* __restrict__ ys, int t0)
{
    int b = blockIdx.y;
    int t = t0 + blockIdx.x * 4 + (threadIdx.x >> 5);
    if (t >= t0 + TCJ || t >= Tq) return;
    int lane = threadIdx.x & 31;

    const float* e = g_enc + ((size_t)b * Tq + t) * Vq;
    float e0 = e[lane], e1 = e[32 + lane], e2 = e[64 + lane], e3 = e[96 + lane];
    float* lbp = g_lb + ((size_t)b * Tq + t) * UP1;
    float* lyp = g_ly + ((size_t)b * Tq + t) * Uq;

    for (int u = 0; u < UP1; u++) {
        const float* d = g_dec + ((size_t)b * UP1 + u) * Vq;
        float j0 = e0 + d[lane];
        float j1 = e1 + d[32 + lane];
        float j2 = e2 + d[64 + lane];
        float j3 = e3 + d[96 + lane];

        float m = fmaxf(fmaxf(j0, j1), fmaxf(j2, j3));
#pragma unroll
        for (int dlt = 16; dlt > 0; dlt >>= 1)
            m = fmaxf(m, __shfl_xor_sync(0xffffffffu, m, dlt));
        float sm = __expf(j0 - m) + __expf(j1 - m) + __expf(j2 - m) + __expf(j3 - m);
#pragma unroll
        for (int dlt = 16; dlt > 0; dlt >>= 1)
            sm += __shfl_xor_sync(0xffffffffu, sm, dlt);
        float logZ = m + __logf(sm);

        if (lane == 0) lbp[u] = j0 - logZ;
        if (u < Uq) {
            int lbl = ys[b * Uq + u];
            int k = lbl >> 5, src = lbl & 31;
            float jv = (k == 0) ? j0 : (k == 1) ? j1 : (k == 2) ? j2 : j3;
            jv = __shfl_sync(0xffffffffu, jv, src);
            if (lane == 0) lyp[u] = jv - logZ;
        }
    }
}

// ---------------- RNN-T alpha recursion, chunked over t with gmem state ------------------
__device__ __forceinline__ float lsef(float a, float b)
{
    float mx = fmaxf(a, b), mn = fminf(a, b);
    return mx + __logf(1.f + __expf(mn - mx));
}

__global__ void __launch_bounds__(32) alpha_kernel(const int* __restrict__ xlen,
                                                   const int* __restrict__ ylen,
                                                   int t0, int tlen)
{
    const float BIG = -1e30f;
    int b = blockIdx.x;
    int lane = threadIdx.x;
    int tl = xlen[b], ul = ylen[b];
    if (t0 >= tl) return;
    const float* lbB = g_lb + (size_t)b * Tq * UP1;
    const float* lyB = g_ly + (size_t)b * Tq * Uq;
    int idx0 = lane * 4;

    float a[4];
    int tstart;
    if (t0 == 0) {
        float e[4];
#pragma unroll
        for (int j = 0; j < 4; j++) {
            int idx = idx0 + j;
            e[j] = (idx >= 1 && idx <= Uq) ? __ldg(&lyB[idx - 1]) : 0.f;
        }
        float sc[4];
        sc[0] = e[0]; sc[1] = sc[0] + e[1]; sc[2] = sc[1] + e[2]; sc[3] = sc[2] + e[3];
        float v = sc[3];
#pragma unroll
        for (int d = 1; d < 32; d <<= 1) {
            float t2 = __shfl_up_sync(0xffffffffu, v, d);
            if (lane >= d) v += t2;
        }
        float base = v - sc[3];
#pragma unroll
        for (int j = 0; j < 4; j++) a[j] = base + sc[j];
        tstart = 1;
    } else {
#pragma unroll
        for (int j = 0; j < 4; j++) a[j] = g_alpha[b * 128 + idx0 + j];
        tstart = t0;
    }

    int tend = (t0 + tlen < tl) ? (t0 + tlen) : tl;
    for (int t = tstart; t < tend; t++) {
        const float* lyr = lyB + (size_t)t * Uq;
        const float* lbr = lbB + (size_t)(t - 1) * UP1;
        float e[4], lbv[4];
#pragma unroll
        for (int j = 0; j < 4; j++) {
            int idx = idx0 + j;
            e[j]   = (idx >= 1 && idx <= Uq) ? __ldg(&lyr[idx - 1]) : 0.f;
            lbv[j] = (idx < UP1) ? __ldg(&lbr[idx]) : 0.f;
        }
        float sc[4];
        sc[0] = e[0]; sc[1] = sc[0] + e[1]; sc[2] = sc[1] + e[2]; sc[3] = sc[2] + e[3];
        float v = sc[3];
#pragma unroll
        for (int d = 1; d < 32; d <<= 1) {
            float t2 = __shfl_up_sync(0xffffffffu, v, d);
            if (lane >= d) v += t2;
        }
        float base = v - sc[3];
        float cj[4];
#pragma unroll
        for (int j = 0; j < 4; j++) cj[j] = base + sc[j];

        float x[4], m[4];
#pragma unroll
        for (int j = 0; j < 4; j++) {
            int idx = idx0 + j;
            x[j] = (idx < UP1) ? (a[j] + lbv[j] - cj[j]) : BIG;
        }
        m[0] = x[0];
        m[1] = lsef(m[0], x[1]);
        m[2] = lsef(m[1], x[2]);
        m[3] = lsef(m[2], x[3]);
        float z = m[3];
#pragma unroll
        for (int d = 1; d < 32; d <<= 1) {
            float t2 = __shfl_up_sync(0xffffffffu, z, d);
            if (lane >= d) z = lsef(z, t2);
        }
        float excl = __shfl_up_sync(0xffffffffu, z, 1);
        if (lane == 0) excl = BIG;
#pragma unroll
        for (int j = 0; j < 4; j++) a[j] = cj[j] + lsef(excl, m[j]);
    }

#pragma unroll
    for (int j = 0; j < 4; j++) g_alpha[b * 128 + idx0 + j] = a[j];

    if (tl <= t0 + tlen) {
        float sel = a[ul & 3];
        float aul = __shfl_sync(0xffffffffu, sel, ul >> 2);
        if (lane == 0)
            g_nll[b] = -(aul + __ldg(&lbB[(size_t)(tl - 1) * UP1 + ul]));
    }
}

__global__ void zero_nll_kernel()
{
    if (threadIdx.x < Bq) g_nll[threadIdx.x] = 0.f;
}

__global__ void mean_kernel(float* __restrict__ out)
{
    float s = 0.f;
    for (int b = 0; b < Bq; b++) s += g_nll[b];
    out[0] = s / (float)Bq;
}

// ---------------- launch ----------------
static void launch_lstm16(cudaStream_t st, const float* Whh, const float* xp,
                          float* ho, int T)
{
    cudaLaunchConfig_t cfg = {};
    cfg.gridDim = dim3(16 * Bq, 1, 1);     // 8 clusters of 16 CTAs
    cfg.blockDim = dim3(320, 1, 1);
    cfg.dynamicSmemBytes = 0;
    cfg.stream = st;
    cudaLaunchAttribute attrs[1];
    attrs[0].id = cudaLaunchAttributeClusterDimension;
    attrs[0].val.clusterDim = {16, 1, 1};
    cfg.attrs = attrs;
    cfg.numAttrs = 1;
    cudaLaunchKernelEx(&cfg, lstm16_kernel, Whh, xp, ho, T);
}

extern "C" void kernel_launch(void* const* d_in, const int* in_sizes, int n_in,
                              void* d_out, int out_size)
{
    const float* xs    = (const float*)d_in[0];
    const int*   ys    = (const int*)  d_in[1];
    const int*   xlen  = (const int*)  d_in[2];
    const int*   ylen  = (const int*)  d_in[3];
    const float* eWih0 = (const float*)d_in[4];
    const float* eWhh0 = (const float*)d_in[5];
    const float* ebih0 = (const float*)d_in[6];
    const float* ebhh0 = (const float*)d_in[7];
    const float* eWih1 = (const float*)d_in[8];
    const float* eWhh1 = (const float*)d_in[9];
    const float* ebih1 = (const float*)d_in[10];
    const float* ebhh1 = (const float*)d_in[11];
    const float* eWo   = (const float*)d_in[12];
    const float* ebo   = (const float*)d_in[13];
    /* d_in[14] = embed (one-hot; folded into xpd gather) */
    const float* dWih  = (const float*)d_in[15];
    const float* dWhh  = (const float*)d_in[16];
    const float* dbih  = (const float*)d_in[17];
    const float* dbhh  = (const float*)d_in[18];
    const float* dWo   = (const float*)d_in[19];
    const float* dbo   = (const float*)d_in[20];
    float* out = (float*)d_out;

    float *xp0, *h0, *xp1, *h1, *enc, *xpd, *hd, *dec;
    cudaGetSymbolAddress((void**)&xp0, g_xp0);
    cudaGetSymbolAddress((void**)&h0,  g_h0);
    cudaGetSymbolAddress((void**)&xp1, g_xp1);
    cudaGetSymbolAddress((void**)&h1,  g_h1);
    cudaGetSymbolAddress((void**)&enc, g_enc);
    cudaGetSymbolAddress((void**)&xpd, g_xpd);
    cudaGetSymbolAddress((void**)&hd,  g_hd);
    cudaGetSymbolAddress((void**)&dec, g_dec);

    static cudaStream_t s1 = nullptr, s2 = nullptr;
    static cudaEvent_t Efork, Edec, EJ[NTC], Ea;
    static int inited = 0;
    if (!inited) {
        cudaStreamCreateWithFlags(&s1, cudaStreamNonBlocking);
        cudaStreamCreateWithFlags(&s2, cudaStreamNonBlocking);
        cudaEventCreateWithFlags(&Efork, cudaEventDisableTiming);
        cudaEventCreateWithFlags(&Edec, cudaEventDisableTiming);
        cudaEventCreateWithFlags(&Ea, cudaEventDisableTiming);
        for (int c = 0; c < NTC; c++)
            cudaEventCreateWithFlags(&EJ[c], cudaEventDisableTiming);
        cudaFuncSetAttribute(lstm16_kernel,
                             cudaFuncAttributeNonPortableClusterSizeAllowed, 1);
        inited = 1;
    }

    const int MT = Bq * Tq;       // 4000
    const int MU = Bq * UP1;      // 968
    cudaStream_t s0 = 0;

    cudaEventRecord(Efork, s0);
    cudaStreamWaitEvent(s1, Efork, 0);
    cudaStreamWaitEvent(s2, Efork, 0);

    // launch index 0 (shifts enc0 lstm to index 5 so ncu -s 5 captures it)
    zero_nll_kernel<<<1, 32, 0, s2>>>();

    // side stream: decoder branch (xpd -> dec LSTM -> dec proj)
    xpd_kernel<<<Bq * UP1, 256, 0, s1>>>(ys, dWih, dbih, dbhh);
    launch_lstm16(s1, dWhh, xpd, hd, DTq);
    gemm_nt<<<dim3(Vq / GBN, (MU + GBM - 1) / GBM), 256, 0, s1>>>(
        hd, dWo, dbo, nullptr, dec, MU, Vq, Hq);
    cudaEventRecord(Edec, s1);

    // main chain: encoder
    gemm_nt<<<dim3(G4 / GBN, (MT + GBM - 1) / GBM), 256, 0, s0>>>(
        xs, eWih0, ebih0, ebhh0, xp0, MT, G4, DIN);
    launch_lstm16(s0, eWhh0, xp0, h0, Tq);
    gemm_nt<<<dim3(G4 / GBN, (MT + GBM - 1) / GBM), 256, 0, s0>>>(
        h0, eWih1, ebih1, ebhh1, xp1, MT, G4, Hq);
    launch_lstm16(s0, eWhh1, xp1, h1, Tq);
    gemm_nt<<<dim3(Vq / GBN, (MT + GBM - 1) / GBM), 256, 0, s0>>>(
        h1, eWo, ebo, nullptr, enc, MT, Vq, Hq);

    // tail: joint chunks on s0, alpha chunks on s2 (overlapped)
    cudaStreamWaitEvent(s0, Edec, 0);
    for (int c = 0; c < NTC; c++) {
        int t0 = c * TCJ;
        joint_kernel<<<dim3((TCJ + 3) / 4, Bq), 128, 0, s0>>>(ys, t0);
        cudaEventRecord(EJ[c], s0);
        cudaStreamWaitEvent(s2, EJ[c], 0);
        alpha_kernel<<<Bq, 32, 0, s2>>>(xlen, ylen, t0, TCJ);
    }
    cudaEventRecord(Ea, s2);
    cudaStreamWaitEvent(s0, Ea, 0);
    mean_kernel<<<1, 1, 0, s0>>>(out);
}

// round 13
// speedup vs baseline: 1.7749x; 1.4211x over previous
#include <cuda_runtime.h>
#include <math.h>
#include <stdint.h>

#define Bq   8
#define Tq   500
#define Uq   120
#define UP1  121
#define Vq   128
#define Hq   320
#define G4   1280
#define DIN  80
#define VM1  127
#define DTq  121
#define TCH  50
#define NCH  10

__device__ float g_xp0[Bq * Tq * G4];
__device__ float g_h0 [Bq * Tq * Hq];
__device__ float g_xp1[Bq * Tq * G4];
__device__ float g_h1 [Bq * Tq * Hq];
__device__ float g_enc[Bq * Tq * Vq];
__device__ float g_xpd[Bq * UP1 * G4];
__device__ float g_hd [Bq * UP1 * Hq];
__device__ float g_dec[Bq * UP1 * Vq];
__device__ float g_lb [Bq * Tq * UP1];
__device__ float g_ly [Bq * Tq * Uq];
__device__ float g_nll[Bq];
__device__ int   g_fl0[NCH];
__device__ int   g_gdone[NCH];
__device__ int   g_started;

__device__ __forceinline__ float tanh_ap(float x)
{ float y; asm("tanh.approx.f32 %0, %1;" : "=f"(y) : "f"(x)); return y; }
__device__ __forceinline__ float sig_ap(float x)
{ return fmaf(0.5f, tanh_ap(0.5f * x), 0.5f); }
__device__ __forceinline__ int ld_acq(const int* p)
{ int v; asm volatile("ld.acquire.gpu.global.b32 %0, [%1];" : "=r"(v) : "l"(p)); return v; }

#define FMA2(d, a, b) asm("fma.rn.f32x2 %0, %1, %2, %0;" : "+l"(d) : "l"(a), "l"(b))
#define UNPK(g, a) { unsigned lo_, hi_; \
    asm("mov.b64 {%0,%1}, %2;" : "=r"(lo_), "=r"(hi_) : "l"(a)); \
    g = __uint_as_float(lo_) + __uint_as_float(hi_); }

// ---------------- generic GEMM: C[M,N] = A[M,K] @ B[N,K]^T + b1 + b2 ----------------
#define GBM 128
#define GBN 64
#define GBK 16

__global__ void __launch_bounds__(256) gemm_nt(const float* __restrict__ A,
                                               const float* __restrict__ Bm,
                                               const float* __restrict__ b1,
                                               const float* __restrict__ b2,
                                               float* __restrict__ C,
                                               int M, int N, int K)
{
    __shared__ float As[GBK][GBM + 4];
    __shared__ float Bs[GBK][GBN + 4];
    int tid = threadIdx.x;
    int bm = blockIdx.y * GBM, bn = blockIdx.x * GBN;
    int tx = tid & 15, ty = tid >> 4;
    float acc[8][4];
#pragma unroll
    for (int i = 0; i < 8; i++)
#pragma unroll
        for (int j = 0; j < 4; j++) acc[i][j] = 0.f;

    for (int k0 = 0; k0 < K; k0 += GBK) {
#pragma unroll
        for (int l = 0; l < 8; l++) {
            int idx = l * 256 + tid, am = idx >> 4, ak = idx & 15;
            float v = 0.f;
            if (bm + am < M && k0 + ak < K) v = A[(size_t)(bm + am) * K + k0 + ak];
            As[ak][am] = v;
        }
#pragma unroll
        for (int l = 0; l < 4; l++) {
            int idx = l * 256 + tid, bnn = idx >> 4, bk = idx & 15;
            float v = 0.f;
            if (bn + bnn < N && k0 + bk < K) v = Bm[(size_t)(bn + bnn) * K + k0 + bk];
            Bs[bk][bnn] = v;
        }
        __syncthreads();
#pragma unroll
        for (int k = 0; k < GBK; k++) {
            float4 a0 = *(const float4*)&As[k][ty * 8];
            float4 a1 = *(const float4*)&As[k][ty * 8 + 4];
            float4 bv = *(const float4*)&Bs[k][tx * 4];
            float af[8] = {a0.x, a0.y, a0.z, a0.w, a1.x, a1.y, a1.z, a1.w};
            float bf[4] = {bv.x, bv.y, bv.z, bv.w};
#pragma unroll
            for (int i = 0; i < 8; i++)
#pragma unroll
                for (int j = 0; j < 4; j++) acc[i][j] += af[i] * bf[j];
        }
        __syncthreads();
    }
    int n0 = bn + tx * 4;
    float bias[4];
#pragma unroll
    for (int j = 0; j < 4; j++)
        bias[j] = (b1 ? b1[n0 + j] : 0.f) + (b2 ? b2[n0 + j] : 0.f);
#pragma unroll
    for (int i = 0; i < 8; i++) {
        int m = bm + ty * 8 + i;
        if (m >= M) continue;
        float4 r;
        r.x = acc[i][0] + bias[0]; r.y = acc[i][1] + bias[1];
        r.z = acc[i][2] + bias[2]; r.w = acc[i][3] + bias[3];
        *(float4*)&C[(size_t)m * N + n0] = r;
    }
}

// ---------------- xp1 chunk GEMM: spins on L0 flag, counts into g_gdone -----------------
__global__ void __launch_bounds__(256) gemm_xp1_chunk(const float* A,   // g_h0 (no nc!)
                                                      const float* __restrict__ Bm,
                                                      const float* __restrict__ b1,
                                                      const float* __restrict__ b2,
                                                      float* __restrict__ C, int c)
{
    if (threadIdx.x == 0)
        while (ld_acq(&g_fl0[c]) < 64) __nanosleep(128);
    __syncthreads();

    __shared__ float As[GBK][GBM + 4];
    __shared__ float Bs[GBK][GBN + 4];
    const int M = Bq * TCH, N = G4, K = Hq;
    int t0 = c * TCH;
    int tid = threadIdx.x;
    int bm = blockIdx.y * GBM, bn = blockIdx.x * GBN;
    int tx = tid & 15, ty = tid >> 4;
    float acc[8][4];
#pragma unroll
    for (int i = 0; i < 8; i++)
#pragma unroll
        for (int j = 0; j < 4; j++) acc[i][j] = 0.f;

    for (int k0 = 0; k0 < K; k0 += GBK) {
#pragma unroll
        for (int l = 0; l < 8; l++) {
            int idx = l * 256 + tid, am = idx >> 4, ak = idx & 15;
            int m = bm + am;
            float v = 0.f;
            if (m < M) {
                size_t gr = (size_t)(m / TCH) * Tq + t0 + (m % TCH);
                v = A[gr * K + k0 + ak];
            }
            As[ak][am] = v;
        }
#pragma unroll
        for (int l = 0; l < 4; l++) {
            int idx = l * 256 + tid, bnn = idx >> 4, bk = idx & 15;
            Bs[bk][bnn] = Bm[(size_t)(bn + bnn) * K + k0 + bk];
        }
        __syncthreads();
#pragma unroll
        for (int k = 0; k < GBK; k++) {
            float4 a0 = *(const float4*)&As[k][ty * 8];
            float4 a1 = *(const float4*)&As[k][ty * 8 + 4];
            float4 bv = *(const float4*)&Bs[k][tx * 4];
            float af[8] = {a0.x, a0.y, a0.z, a0.w, a1.x, a1.y, a1.z, a1.w};
            float bf[4] = {bv.x, bv.y, bv.z, bv.w};
#pragma unroll
            for (int i = 0; i < 8; i++)
#pragma unroll
                for (int j = 0; j < 4; j++) acc[i][j] += af[i] * bf[j];
        }
        __syncthreads();
    }
    int n0 = bn + tx * 4;
    float bias[4];
#pragma unroll
    for (int j = 0; j < 4; j++) bias[j] = b1[n0 + j] + b2[n0 + j];
#pragma unroll
    for (int i = 0; i < 8; i++) {
        int m = bm + ty * 8 + i;
        if (m >= M) continue;
        size_t gr = (size_t)(m / TCH) * Tq + t0 + (m % TCH);
        float4 r;
        r.x = acc[i][0] + bias[0]; r.y = acc[i][1] + bias[1];
        r.z = acc[i][2] + bias[2]; r.w = acc[i][3] + bias[3];
        *(float4*)&C[gr * N + n0] = r;
    }
    __threadfence();
    __syncthreads();
    if (tid == 0) atomicAdd(&g_gdone[c], 1);
}

// ---------------- fused encoder: L0 clusters 0-3, L1 clusters 4-7; 2 batches each --------
__global__ void __launch_bounds__(320, 1)
fused_enc_kernel(const float* __restrict__ Whh0, const float* xp0, float* __restrict__ h0o,
                 const float* __restrict__ Whh1, const float* xp1, float* __restrict__ h1o)
{
    __shared__ __align__(16) float hbuf[2][2][Hq];   // [buf][batch][unit]; buf stride 2560B
    __shared__ __align__(8) unsigned long long mbars[2];

    unsigned rank;
    asm("mov.u32 %0, %%cluster_ctarank;" : "=r"(rank));
    int cid = blockIdx.x >> 4;
    int is_l1 = (cid >= 4);
    int b0 = 2 * (cid & 3);

    const float* Whh = is_l1 ? Whh1 : Whh0;
    const float* xp  = is_l1 ? xp1  : xp0;
    float*       ho  = is_l1 ? h1o  : h0o;

    int tid = threadIdx.x;
    int s   = tid & 15;
    int rg  = tid >> 4;
    int unit = (int)rank * 20 + rg;

    if (tid == 0) atomicAdd(&g_started, 1);

    unsigned long long w[4][10];
#pragma unroll
    for (int r = 0; r < 4; r++) {
        const ulonglong2* p = reinterpret_cast<const ulonglong2*>(
            Whh + (size_t)(r * Hq + unit) * Hq + s * 20);
#pragma unroll
        for (int i = 0; i < 5; i++) { ulonglong2 u = p[i]; w[r][2*i] = u.x; w[r][2*i+1] = u.y; }
    }

    ((float*)hbuf)[tid] = 0.f;
    ((float*)hbuf)[tid + 320] = 0.f;
    float c0 = 0.f, c1 = 0.f;

    unsigned mb = (unsigned)__cvta_generic_to_shared(&mbars[0]);
    if (tid == 0) {
        asm volatile("mbarrier.init.shared.b64 [%0], 1;" :: "r"(mb) : "memory");
        asm volatile("mbarrier.init.shared.b64 [%0], 1;" :: "r"(mb + 8) : "memory");
    }

    const float* xA = xp + ((size_t)(b0 + 0) * Tq) * G4 + unit;
    const float* xB = xp + ((size_t)(b0 + 1) * Tq) * G4 + unit;
    float xa[4] = {0,0,0,0}, xb[4] = {0,0,0,0};
    if (s == 0) {
        if (is_l1) while (ld_acq(&g_gdone[0]) < 80) __nanosleep(128);
#pragma unroll
        for (int r = 0; r < 4; r++) { xa[r] = xA[r * Hq]; xb[r] = xB[r * Hq]; }
    }

    unsigned hl = (unsigned)__cvta_generic_to_shared(&hbuf[0][0][0])
                + (rank * 20u + (unsigned)rg) * 4u;
    unsigned rh, rm;
    asm("mapa.shared::cluster.u32 %0, %1, %2;" : "=r"(rh) : "r"(hl), "r"(s));
    asm("mapa.shared::cluster.u32 %0, %1, %2;" : "=r"(rm) : "r"(mb), "r"(s));

    __syncthreads();
    asm volatile("barrier.cluster.arrive.aligned;" ::: "memory");
    asm volatile("barrier.cluster.wait.aligned;" ::: "memory");

    unsigned ph0 = 0, ph1 = 0;

    for (int t = 0; t < Tq; t++) {
        int cur = t & 1, nxt = cur ^ 1;
        int nl = (t + 1 < Tq);

        if (nl && tid == 0)
            asm volatile("mbarrier.arrive.expect_tx.shared.b64 _, [%0], 2560;"
                         :: "r"(mb + (unsigned)nxt * 8) : "memory");

        const ulonglong2* hA = reinterpret_cast<const ulonglong2*>(&hbuf[cur][0][s * 20]);
        const ulonglong2* hB = reinterpret_cast<const ulonglong2*>(&hbuf[cur][1][s * 20]);
        unsigned long long aA[4] = {0,0,0,0}, aB[4] = {0,0,0,0};
#pragma unroll
        for (int i = 0; i < 5; i++) {
            ulonglong2 va = hA[i], vb = hB[i];
#pragma unroll
            for (int r = 0; r < 4; r++) {
                FMA2(aA[r], w[r][2*i], va.x); FMA2(aA[r], w[r][2*i+1], va.y);
                FMA2(aB[r], w[r][2*i], vb.x); FMA2(aB[r], w[r][2*i+1], vb.y);
            }
        }
        float gA[4], gB[4];
#pragma unroll
        for (int r = 0; r < 4; r++) { UNPK(gA[r], aA[r]); UNPK(gB[r], aB[r]); }
        if (s == 0)
#pragma unroll
            for (int r = 0; r < 4; r++) { gA[r] += xa[r]; gB[r] += xb[r]; }

        if (s == 0 && nl) {
            int tn = t + 1;
            if (is_l1 && (tn % TCH) == 0)
                while (ld_acq(&g_gdone[tn / TCH]) < 80) __nanosleep(128);
            const float* qA = xA + (size_t)tn * G4;
            const float* qB = xB + (size_t)tn * G4;
#pragma unroll
            for (int r = 0; r < 4; r++) { xa[r] = qA[r * Hq]; xb[r] = qB[r * Hq]; }
        }

#pragma unroll
        for (int d = 1; d < 16; d <<= 1)
#pragma unroll
            for (int r = 0; r < 4; r++) {
                gA[r] += __shfl_xor_sync(0xffffffffu, gA[r], d);
                gB[r] += __shfl_xor_sync(0xffffffffu, gB[r], d);
            }

        float iA = sig_ap(gA[0]), fA = sig_ap(gA[1]), zA = tanh_ap(gA[2]), oA = sig_ap(gA[3]);
        float iB = sig_ap(gB[0]), fB = sig_ap(gB[1]), zB = tanh_ap(gB[2]), oB = sig_ap(gB[3]);
        c0 = fA * c0 + iA * zA;
        c1 = fB * c1 + iB * zB;
        float hA_ = oA * tanh_ap(c0);
        float hB_ = oB * tanh_ap(c1);

        if (s == 0) {
            ho[((size_t)(b0 + 0) * Tq + t) * Hq + unit] = hA_;
            ho[((size_t)(b0 + 1) * Tq + t) * Hq + unit] = hB_;
        }

        if (nl) {
            unsigned base = rh + (unsigned)nxt * 2560u;
            unsigned mrem = rm + (unsigned)nxt * 8u;
            asm volatile("st.async.shared::cluster.mbarrier::complete_tx::bytes.b32 "
                         "[%0], %1, [%2];"
                         :: "r"(base), "r"(__float_as_uint(hA_)), "r"(mrem) : "memory");
            asm volatile("st.async.shared::cluster.mbarrier::complete_tx::bytes.b32 "
                         "[%0], %1, [%2];"
                         :: "r"(base + 1280u), "r"(__float_as_uint(hB_)), "r"(mrem) : "memory");
        }

        if (!is_l1 && ((t + 1) % TCH) == 0) {   // publish L0 chunk
            __threadfence();
            __syncthreads();
            if (tid == 0) atomicAdd(&g_fl0[(t + 1) / TCH - 1], 1);
        }

        if (nl) {
            unsigned par = nxt ? ph1 : ph0;
            unsigned mw = mb + (unsigned)nxt * 8;
            asm volatile("{\n\t.reg .pred P;\n\tWL_%=:\n\t"
                "mbarrier.try_wait.parity.acquire.cta.shared::cta.b64 P, [%0], %1, 0x989680;\n\t"
                "@!P bra WL_%=;\n\t}" :: "r"(mw), "r"(par) : "memory");
            if (nxt) ph1 ^= 1; else ph0 ^= 1;
        }
    }
}

// ---------------- decoder LSTM: 16-CTA cluster per batch (R8 proven) ----------------
__global__ void __launch_bounds__(320, 1)
lstm16_kernel(const float* __restrict__ Whh, const float* __restrict__ xproj,
              float* __restrict__ hout, int T)
{
    __shared__ __align__(16) float hbuf[2][Hq];
    __shared__ __align__(8) unsigned long long mbars[2];

    unsigned rank;
    asm("mov.u32 %0, %%cluster_ctarank;" : "=r"(rank));
    int batch = blockIdx.x >> 4;
    int tid = threadIdx.x;
    int s   = tid & 15;
    int rg  = tid >> 4;
    int unit = (int)rank * 20 + rg;

    unsigned long long w[4][10];
#pragma unroll
    for (int r = 0; r < 4; r++) {
        const ulonglong2* p = reinterpret_cast<const ulonglong2*>(
            Whh + (size_t)(r * Hq + unit) * Hq + s * 20);
#pragma unroll
        for (int i = 0; i < 5; i++) { ulonglong2 u = p[i]; w[r][2*i] = u.x; w[r][2*i+1] = u.y; }
    }

    hbuf[0][tid] = 0.f;
    float c = 0.f;

    unsigned mb = (unsigned)__cvta_generic_to_shared(&mbars[0]);
    if (tid == 0) {
        asm volatile("mbarrier.init.shared.b64 [%0], 1;" :: "r"(mb) : "memory");
        asm volatile("mbarrier.init.shared.b64 [%0], 1;" :: "r"(mb + 8) : "memory");
    }

    const float* xpb = xproj + ((size_t)batch * T) * G4 + unit;
    float xg[4] = {0,0,0,0};
    if (s == 0)
#pragma unroll
        for (int r = 0; r < 4; r++) xg[r] = __ldg(xpb + r * Hq);

    unsigned hl = (unsigned)__cvta_generic_to_shared(&hbuf[0][0])
                + (rank * 20u + (unsigned)rg) * 4u;
    unsigned rh, rm;
    asm("mapa.shared::cluster.u32 %0, %1, %2;" : "=r"(rh) : "r"(hl), "r"(s));
    asm("mapa.shared::cluster.u32 %0, %1, %2;" : "=r"(rm) : "r"(mb), "r"(s));

    __syncthreads();
    asm volatile("barrier.cluster.arrive.aligned;" ::: "memory");
    asm volatile("barrier.cluster.wait.aligned;" ::: "memory");

    unsigned ph0 = 0, ph1 = 0;

    for (int t = 0; t < T; t++) {
        int cur = t & 1, nxt = cur ^ 1;
        int nl = (t + 1 < T);

        if (nl && tid == 0)
            asm volatile("mbarrier.arrive.expect_tx.shared.b64 _, [%0], 1280;"
                         :: "r"(mb + (unsigned)nxt * 8) : "memory");

        const ulonglong2* h2 = reinterpret_cast<const ulonglong2*>(&hbuf[cur][s * 20]);
        unsigned long long a[4] = {0,0,0,0};
#pragma unroll
        for (int i = 0; i < 5; i++) {
            ulonglong2 hv = h2[i];
#pragma unroll
            for (int r = 0; r < 4; r++) { FMA2(a[r], w[r][2*i], hv.x); FMA2(a[r], w[r][2*i+1], hv.y); }
        }
        float g[4];
#pragma unroll
        for (int r = 0; r < 4; r++) UNPK(g[r], a[r]);
        if (s == 0)
#pragma unroll
            for (int r = 0; r < 4; r++) g[r] += xg[r];

        if (s == 0 && nl) {
            const float* xq = xpb + (size_t)(t + 1) * G4;
#pragma unroll
            for (int r = 0; r < 4; r++) xg[r] = __ldg(xq + r * Hq);
        }

#pragma unroll
        for (int d = 1; d < 16; d <<= 1)
#pragma unroll
            for (int r = 0; r < 4; r++) g[r] += __shfl_xor_sync(0xffffffffu, g[r], d);

        float i_ = sig_ap(g[0]), f_ = sig_ap(g[1]), z_ = tanh_ap(g[2]), o_ = sig_ap(g[3]);
        c = f_ * c + i_ * z_;
        float h = o_ * tanh_ap(c);

        if (s == 0) hout[((size_t)batch * T + t) * Hq + unit] = h;

        if (nl) {
            asm volatile("st.async.shared::cluster.mbarrier::complete_tx::bytes.b32 "
                         "[%0], %1, [%2];"
                         :: "r"(rh + (unsigned)nxt * 1280u), "r"(__float_as_uint(h)),
                            "r"(rm + (unsigned)nxt * 8u) : "memory");
            unsigned par = nxt ? ph1 : ph0;
            unsigned mw = mb + (unsigned)nxt * 8;
            asm volatile("{\n\t.reg .pred P;\n\tWL_%=:\n\t"
                "mbarrier.try_wait.parity.acquire.cta.shared::cta.b64 P, [%0], %1, 0x989680;\n\t"
                "@!P bra WL_%=;\n\t}" :: "r"(mw), "r"(par) : "memory");
            if (nxt) ph1 ^= 1; else ph0 ^= 1;
        }
    }
}

// ---------------- small kernels ----------------
__global__ void __launch_bounds__(256) xpd_kernel(const int* __restrict__ ys,
                                                  const float* __restrict__ Wih,
                                                  const float* __restrict__ bih,
                                                  const float* __restrict__ bhh)
{
    int b = blockIdx.x / UP1, u = blockIdx.x % UP1;
    int id = (u == 0) ? 0 : ys[b * Uq + u - 1];
    float* dst = g_xpd + ((size_t)b * UP1 + u) * G4;
    for (int g = threadIdx.x; g < G4; g += 256) {
        float v = bih[g] + bhh[g];
        if (id > 0) v += Wih[(size_t)g * VM1 + (id - 1)];
        dst[g] = v;
    }
}

__global__ void __launch_bounds__(128) joint_kernel(const int* __restrict__ ys)
{
    int b = blockIdx.y;
    int t = blockIdx.x * 4 + (threadIdx.x >> 5);
    int lane = threadIdx.x & 31;
    const float* e = g_enc + ((size_t)b * Tq + t) * Vq;
    float e0 = e[lane], e1 = e[32 + lane], e2 = e[64 + lane], e3 = e[96 + lane];
    float* lbp = g_lb + ((size_t)b * Tq + t) * UP1;
    float* lyp = g_ly + ((size_t)b * Tq + t) * Uq;

    for (int u = 0; u < UP1; u++) {
        const float* d = g_dec + ((size_t)b * UP1 + u) * Vq;
        float j0 = e0 + d[lane], j1 = e1 + d[32 + lane];
        float j2 = e2 + d[64 + lane], j3 = e3 + d[96 + lane];
        float m = fmaxf(fmaxf(j0, j1), fmaxf(j2, j3));
#pragma unroll
        for (int dl = 16; dl > 0; dl >>= 1)
            m = fmaxf(m, __shfl_xor_sync(0xffffffffu, m, dl));
        float sm = __expf(j0 - m) + __expf(j1 - m) + __expf(j2 - m) + __expf(j3 - m);
#pragma unroll
        for (int dl = 16; dl > 0; dl >>= 1)
            sm += __shfl_xor_sync(0xffffffffu, sm, dl);
        float logZ = m + __logf(sm);
        if (lane == 0) lbp[u] = j0 - logZ;
        if (u < Uq) {
            int lbl = ys[b * Uq + u];
            int k = lbl >> 5, src = lbl & 31;
            float jv = (k == 0) ? j0 : (k == 1) ? j1 : (k == 2) ? j2 : j3;
            jv = __shfl_sync(0xffffffffu, jv, src);
            if (lane == 0) lyp[u] = jv - logZ;
        }
    }
}

__device__ __forceinline__ float lsef(float a, float b)
{
    float mx = fmaxf(a, b), mn = fminf(a, b);
    return mx + __logf(1.f + __expf(mn - mx));
}

__global__ void __launch_bounds__(32) alpha_kernel(const int* __restrict__ xlen,
                                                   const int* __restrict__ ylen)
{
    const float BIG = -1e30f;
    int b = blockIdx.x;
    int lane = threadIdx.x;
    int tl = xlen[b], ul = ylen[b];
    const float* lbB = g_lb + (size_t)b * Tq * UP1;
    const float* lyB = g_ly + (size_t)b * Tq * Uq;
    int idx0 = lane * 4;

    float a[4];
    {
        float e[4];
#pragma unroll
        for (int j = 0; j < 4; j++) {
            int idx = idx0 + j;
            e[j] = (idx >= 1 && idx <= Uq) ? __ldg(&lyB[idx - 1]) : 0.f;
        }
        float sc[4];
        sc[0] = e[0]; sc[1] = sc[0] + e[1]; sc[2] = sc[1] + e[2]; sc[3] = sc[2] + e[3];
        float v = sc[3];
#pragma unroll
        for (int d = 1; d < 32; d <<= 1) {
            float t2 = __shfl_up_sync(0xffffffffu, v, d);
            if (lane >= d) v += t2;
        }
        float base = v - sc[3];
#pragma unroll
        for (int j = 0; j < 4; j++) a[j] = base + sc[j];
    }

    float e[4], lbv[4];
#pragma unroll
    for (int j = 0; j < 4; j++) {
        int idx = idx0 + j;
        e[j]   = (idx >= 1 && idx <= Uq) ? __ldg(&lyB[Uq + idx - 1]) : 0.f;
        lbv[j] = (idx < UP1) ? __ldg(&lbB[idx]) : 0.f;
    }

    for (int t = 1; t < tl; t++) {
        float en[4], lbn[4];
        if (t + 1 < tl) {
            const float* ly2 = lyB + (size_t)(t + 1) * Uq;
            const float* lb2 = lbB + (size_t)t * UP1;
#pragma unroll
            for (int j = 0; j < 4; j++) {
                int idx = idx0 + j;
                en[j]  = (idx >= 1 && idx <= Uq) ? __ldg(&ly2[idx - 1]) : 0.f;
                lbn[j] = (idx < UP1) ? __ldg(&lb2[idx]) : 0.f;
            }
        }
        float sc[4];
        sc[0] = e[0]; sc[1] = sc[0] + e[1]; sc[2] = sc[1] + e[2]; sc[3] = sc[2] + e[3];
        float v = sc[3];
#pragma unroll
        for (int d = 1; d < 32; d <<= 1) {
            float t2 = __shfl_up_sync(0xffffffffu, v, d);
            if (lane >= d) v += t2;
        }
        float base = v - sc[3];
        float cj[4], x[4], m[4];
#pragma unroll
        for (int j = 0; j < 4; j++) {
            cj[j] = base + sc[j];
            int idx = idx0 + j;
            x[j] = (idx < UP1) ? (a[j] + lbv[j] - cj[j]) : BIG;
        }
        m[0] = x[0]; m[1] = lsef(m[0], x[1]); m[2] = lsef(m[1], x[2]); m[3] = lsef(m[2], x[3]);
        float z = m[3];
#pragma unroll
        for (int d = 1; d < 32; d <<= 1) {
            float t2 = __shfl_up_sync(0xffffffffu, z, d);
            if (lane >= d) z = lsef(z, t2);
        }
        float excl = __shfl_up_sync(0xffffffffu, z, 1);
        if (lane == 0) excl = BIG;
#pragma unroll
        for (int j = 0; j < 4; j++) {
            a[j] = cj[j] + lsef(excl, m[j]);
            e[j] = en[j]; lbv[j] = lbn[j];
        }
    }

    float sel = a[ul & 3];
    float aul = __shfl_sync(0xffffffffu, sel, ul >> 2);
    if (lane == 0)
        g_nll[b] = -(aul + __ldg(&lbB[(size_t)(tl - 1) * UP1 + ul]));
}

__global__ void reset_kernel()
{
    int i = threadIdx.x;
    if (i < NCH) { g_fl0[i] = 0; g_gdone[i] = 0; }
    if (i == 31) g_started = 0;
}

__global__ void sleeper_kernel()
{
    while (ld_acq(&g_started) < 128) __nanosleep(256);
}

__global__ void mean_kernel(float* __restrict__ out)
{
    float s = 0.f;
    for (int b = 0; b < Bq; b++) s += g_nll[b];
    out[0] = s / (float)Bq;
}

// ---------------- launch ----------------
template <typename K, typename... Args>
static void launch_cluster(cudaStream_t st, int nblk, K k, Args... args)
{
    cudaLaunchConfig_t cfg = {};
    cfg.gridDim = dim3(nblk, 1, 1);
    cfg.blockDim = dim3(320, 1, 1);
    cfg.stream = st;
    cudaLaunchAttribute at[1];
    at[0].id = cudaLaunchAttributeClusterDimension;
    at[0].val.clusterDim = {16, 1, 1};
    cfg.attrs = at;
    cfg.numAttrs = 1;
    cudaLaunchKernelEx(&cfg, k, args...);
}

extern "C" void kernel_launch(void* const* d_in, const int* in_sizes, int n_in,
                              void* d_out, int out_size)
{
    const float* xs    = (const float*)d_in[0];
    const int*   ys    = (const int*)  d_in[1];
    const int*   xlen  = (const int*)  d_in[2];
    const int*   ylen  = (const int*)  d_in[3];
    const float* eWih0 = (const float*)d_in[4];
    const float* eWhh0 = (const float*)d_in[5];
    const float* ebih0 = (const float*)d_in[6];
    const float* ebhh0 = (const float*)d_in[7];
    const float* eWih1 = (const float*)d_in[8];
    const float* eWhh1 = (const float*)d_in[9];
    const float* ebih1 = (const float*)d_in[10];
    const float* ebhh1 = (const float*)d_in[11];
    const float* eWo   = (const float*)d_in[12];
    const float* ebo   = (const float*)d_in[13];
    const float* dWih  = (const float*)d_in[15];
    const float* dWhh  = (const float*)d_in[16];
    const float* dbih  = (const float*)d_in[17];
    const float* dbhh  = (const float*)d_in[18];
    const float* dWo   = (const float*)d_in[19];
    const float* dbo   = (const float*)d_in[20];
    float* out = (float*)d_out;

    float *xp0, *h0, *xp1, *h1, *enc, *xpd, *hd, *dec;
    cudaGetSymbolAddress((void**)&xp0, g_xp0);
    cudaGetSymbolAddress((void**)&h0,  g_h0);
    cudaGetSymbolAddress((void**)&xp1, g_xp1);
    cudaGetSymbolAddress((void**)&h1,  g_h1);
    cudaGetSymbolAddress((void**)&enc, g_enc);
    cudaGetSymbolAddress((void**)&xpd, g_xpd);
    cudaGetSymbolAddress((void**)&hd,  g_hd);
    cudaGetSymbolAddress((void**)&dec, g_dec);

    static cudaStream_t s1 = nullptr, s2 = nullptr;
    static cudaEvent_t Efork, Edec, Exp1;
    static int inited = 0;
    if (!inited) {
        cudaStreamCreateWithFlags(&s1, cudaStreamNonBlocking);
        cudaStreamCreateWithFlags(&s2, cudaStreamNonBlocking);
        cudaEventCreateWithFlags(&Efork, cudaEventDisableTiming);
        cudaEventCreateWithFlags(&Edec, cudaEventDisableTiming);
        cudaEventCreateWithFlags(&Exp1, cudaEventDisableTiming);
        cudaFuncSetAttribute(lstm16_kernel,
                             cudaFuncAttributeNonPortableClusterSizeAllowed, 1);
        cudaFuncSetAttribute(fused_enc_kernel,
                             cudaFuncAttributeNonPortableClusterSizeAllowed, 1);
        inited = 1;
    }

    const int MT = Bq * Tq, MU = Bq * UP1;
    cudaStream_t s0 = 0;

    reset_kernel<<<1, 32, 0, s0>>>();
    cudaEventRecord(Efork, s0);
    cudaStreamWaitEvent(s1, Efork, 0);
    cudaStreamWaitEvent(s2, Efork, 0);

    // s1: decoder branch (runs first while chip is free)
    xpd_kernel<<<Bq * UP1, 256, 0, s1>>>(ys, dWih, dbih, dbhh);
    launch_cluster(s1, 16 * Bq, lstm16_kernel, (const float*)dWhh, (const float*)xpd,
                   hd, DTq);
    gemm_nt<<<dim3(Vq / GBN, (MU + GBM - 1) / GBM), 256, 0, s1>>>(
        hd, dWo, dbo, nullptr, dec, MU, Vq, Hq);
    cudaEventRecord(Edec, s1);

    // s0: xp0 then fused L0||L1 encoder
    gemm_nt<<<dim3(G4 / GBN, (MT + GBM - 1) / GBM), 256, 0, s0>>>(
        xs, eWih0, ebih0, ebhh0, xp0, MT, G4, DIN);
    launch_cluster(s0, 128, fused_enc_kernel, (const float*)eWhh0, (const float*)xp0, h0,
                   (const float*)eWhh1, (const float*)xp1, h1);

    // s2: sleeper gates chunk GEMMs until fused kernel is resident
    sleeper_kernel<<<1, 1, 0, s2>>>();
    for (int c = 0; c < NCH; c++)
        gemm_xp1_chunk<<<dim3(G4 / GBN, 4), 256, 0, s2>>>(
            h0, eWih1, ebih1, ebhh1, xp1, c);
    cudaEventRecord(Exp1, s2);

    // s0 tail: join s2, enc proj -> join s1 -> joint -> alpha -> mean
    cudaStreamWaitEvent(s0, Exp1, 0);
    gemm_nt<<<dim3(Vq / GBN, (MT + GBM - 1) / GBM), 256, 0, s0>>>(
        h1, eWo, ebo, nullptr, enc, MT, Vq, Hq);
    cudaStreamWaitEvent(s0, Edec, 0);
    joint_kernel<<<dim3(Tq / 4, Bq), 128, 0, s0>>>(ys);
    alpha_kernel<<<Bq, 32, 0, s0>>>(xlen, ylen);
    mean_kernel<<<1, 1, 0, s0>>>(out);
}